// round 13
// baseline (speedup 1.0000x reference)
#include <cuda_runtime.h>
#include <cuda_fp16.h>
#include <math.h>
#include <stdint.h>

#define BATCH 4
#define CDIM  256
#define CHALF 128
#define NPIX  4096

// ---- scratch (device globals; no dynamic allocation allowed) ----
__device__ __half d_wb [3 * CHALF * CDIM];            // w1|w2|w3 f16 [3][128][256]
__device__ __half d_w4b[CDIM * CHALF];                // w4 f16 [256][128]
__device__ __half d_xT [BATCH * NPIX * CDIM];         // x^T [b][n][c] f16
__device__ __half d_thT[BATCH * NPIX * CHALF];        // theta^T [b][i][c] f16
__device__ __half d_phT[BATCH * NPIX * CHALF];        // phi^T   [b][j][c] f16
__device__ __half d_gu [BATCH * CHALF * NPIX];        // g unscaled [b][c][j] f16
__device__ __align__(128) uint8_t d_gs8[BATCH * CHALF * NPIX];  // g*4096/den e4m3 [b][c][j]
__device__ float  d_denp[BATCH * 32 * NPIX];
__device__ __align__(128) uint8_t d_E[(size_t)BATCH * NPIX * NPIX]; // exp(scores) e4m3, 64 MB

// ================= helpers =================
__device__ __forceinline__ uint32_t smem_u32(const void* p) {
    uint32_t a;
    asm("{ .reg .u64 t; cvta.to.shared.u64 t, %1; cvt.u32.u64 %0, t; }" : "=r"(a) : "l"(p));
    return a;
}
__device__ __forceinline__ uint32_t pack_f16x2(float lo, float hi) {
    __half2 h = __floats2half2_rn(lo, hi);
    return *(uint32_t*)&h;
}
__device__ __forceinline__ uint16_t pack_e4m3x2(float lo, float hi) {
    uint16_t r;
    asm("cvt.rn.satfinite.e4m3x2.f32 %0, %1, %2;" : "=h"(r) : "f"(hi), "f"(lo));
    return r;
}
__device__ __forceinline__ void ldm_x4(uint32_t& r0, uint32_t& r1, uint32_t& r2, uint32_t& r3,
                                       uint32_t addr) {
    asm volatile("ldmatrix.sync.aligned.m8n8.x4.shared.b16 {%0,%1,%2,%3}, [%4];"
                 : "=r"(r0), "=r"(r1), "=r"(r2), "=r"(r3) : "r"(addr));
}
__device__ __forceinline__ void mma_f16(float* c, const uint32_t* a, const uint32_t* b) {
    asm volatile(
        "mma.sync.aligned.m16n8k16.row.col.f32.f16.f16.f32 "
        "{%0,%1,%2,%3}, {%4,%5,%6,%7}, {%8,%9}, {%0,%1,%2,%3};"
        : "+f"(c[0]), "+f"(c[1]), "+f"(c[2]), "+f"(c[3])
        : "r"(a[0]), "r"(a[1]), "r"(a[2]), "r"(a[3]), "r"(b[0]), "r"(b[1]));
}
__device__ __forceinline__ void mma_f16acc(uint32_t* c, const uint32_t* a, const uint32_t* b) {
    asm volatile(
        "mma.sync.aligned.m16n8k16.row.col.f16.f16.f16.f16 "
        "{%0,%1}, {%2,%3,%4,%5}, {%6,%7}, {%0,%1};"
        : "+r"(c[0]), "+r"(c[1])
        : "r"(a[0]), "r"(a[1]), "r"(a[2]), "r"(a[3]), "r"(b[0]), "r"(b[1]));
}
__device__ __forceinline__ void mma_e4m3(float* c, const uint32_t* a, const uint32_t* b) {
    asm volatile(
        "mma.sync.aligned.m16n8k32.row.col.f32.e4m3.e4m3.f32 "
        "{%0,%1,%2,%3}, {%4,%5,%6,%7}, {%8,%9}, {%0,%1,%2,%3};"
        : "+f"(c[0]), "+f"(c[1]), "+f"(c[2]), "+f"(c[3])
        : "r"(a[0]), "r"(a[1]), "r"(a[2]), "r"(a[3]), "r"(b[0]), "r"(b[1]));
}
__device__ __forceinline__ void cp16(uint32_t dst, const void* src) {
    asm volatile("cp.async.cg.shared.global [%0], [%1], 16;" :: "r"(dst), "l"(src) : "memory");
}
__device__ __forceinline__ void cp_commit() { asm volatile("cp.async.commit_group;" ::: "memory"); }
__device__ __forceinline__ void cp_wait0()  { asm volatile("cp.async.wait_group 0;" ::: "memory"); }
__device__ __forceinline__ void cp_wait1()  { asm volatile("cp.async.wait_group 1;" ::: "memory"); }

#define SROW 272   // 128 f16 row + 16B pad
#define PROW 528   // 256 f16 row + 16B pad
#define FROW 144   // 128 fp8 row + 16B pad

// ============================================================
// Kernel 0a: weight convert to f16
// ============================================================
__global__ void wconv_kernel(const float* __restrict__ w1, const float* __restrict__ w2,
                             const float* __restrict__ w3, const float* __restrict__ w4)
{
    int idx = blockIdx.x * 256 + threadIdx.x;   // 131072 total
    if (idx < 98304) {
        int sel = idx >> 15, r = idx & 32767;
        const float* W = (sel == 0) ? w1 : (sel == 1) ? w2 : w3;
        d_wb[idx] = __float2half(W[r]);
    } else {
        int r = idx - 98304;
        d_w4b[r] = __float2half(w4[r]);
    }
}

// ============================================================
// Kernel 0b: x transpose-convert: [b][c][n] fp32 -> [b][n][c] f16
// ============================================================
__global__ void xT_kernel(const float* __restrict__ x)
{
    __shared__ float t[32][33];
    const int n0 = blockIdx.x * 32, c0 = blockIdx.y * 32, b = blockIdx.z;
    const float* xb = x + ((size_t)b * CDIM + c0) * NPIX + n0;
    for (int r = threadIdx.y; r < 32; r += 8)
        t[r][threadIdx.x] = xb[(size_t)r * NPIX + threadIdx.x];
    __syncthreads();
    __half* o = d_xT + ((size_t)b * NPIX + n0) * CDIM + c0;
    for (int r = threadIdx.y; r < 32; r += 8)
        o[(size_t)r * CDIM + threadIdx.x] = __float2half(t[threadIdx.x][r]);
}

// ============================================================
// Kernel 1: proj via mma (f16 in, f32 acc). M=128, N=128, K=256.
// sel 0/1 -> thT/phT f16 [n][m]; sel 2 -> gu f16 [m][n].
// ============================================================
__global__ __launch_bounds__(256) void proj_mma_kernel(
    const float* __restrict__ b1, const float* __restrict__ b2, const float* __restrict__ b3)
{
    extern __shared__ __align__(16) char smem[];
    char* Asm = smem;               // 128*528 = 67584
    char* Bsm = smem + 67584;
    const uint32_t Asb = smem_u32(Asm), Bsb = smem_u32(Bsm);

    const int tid = threadIdx.x, wid = tid >> 5, lane = tid & 31;
    const int n0 = blockIdx.x * 128, sel = blockIdx.y, b = blockIdx.z;
    const float* Bv = (sel == 0) ? b1 : (sel == 1) ? b2 : b3;

    const __half* W = d_wb + (size_t)sel * CHALF * CDIM;
    const __half* X = d_xT + ((size_t)b * NPIX + n0) * CDIM;

#pragma unroll
    for (int e = 0; e < 16; ++e) {
        int idx = e * 256 + tid;
        int row = idx >> 5, kb = idx & 31;
        cp16(Asb + row * PROW + kb * 16, W + (size_t)row * CDIM + kb * 8);
        cp16(Bsb + row * PROW + kb * 16, X + (size_t)row * CDIM + kb * 8);
    }
    cp_commit(); cp_wait0();
    __syncthreads();

    const int wm = (wid & 3) * 32, wn = (wid >> 2) * 64;
    const int id = lane >> 3, l7 = lane & 7;

    float acc[2][8][4];
#pragma unroll
    for (int am = 0; am < 2; ++am)
#pragma unroll
        for (int an = 0; an < 8; ++an)
#pragma unroll
            for (int q = 0; q < 4; ++q) acc[am][an][q] = 0.f;

#pragma unroll
    for (int ks = 0; ks < 16; ++ks) {
        uint32_t a[2][4];
#pragma unroll
        for (int am = 0; am < 2; ++am) {
            uint32_t addr = Asb + (uint32_t)(wm + am * 16 + (id & 1) * 8 + l7) * PROW
                          + (uint32_t)(ks * 16 + (id >> 1) * 8) * 2;
            ldm_x4(a[am][0], a[am][1], a[am][2], a[am][3], addr);
        }
        uint32_t bf[8][2];
#pragma unroll
        for (int p = 0; p < 4; ++p) {
            uint32_t r0, r1, r2, r3;
            uint32_t addr = Bsb + (uint32_t)(wn + p * 16 + (id >> 1) * 8 + l7) * PROW
                          + (uint32_t)(ks * 16 + (id & 1) * 8) * 2;
            ldm_x4(r0, r1, r2, r3, addr);
            bf[p * 2][0] = r0; bf[p * 2][1] = r1;
            bf[p * 2 + 1][0] = r2; bf[p * 2 + 1][1] = r3;
        }
#pragma unroll
        for (int am = 0; am < 2; ++am)
#pragma unroll
            for (int an = 0; an < 8; ++an)
                mma_f16(acc[am][an], a[am], bf[an]);
    }
    __syncthreads();

    char* Es = smem;
    const int gID = lane >> 2, tig = lane & 3;

    if (sel < 2) {
        // stage transposed [n][m] f16 (stride 272), bias per m
#pragma unroll
        for (int am = 0; am < 2; ++am) {
            float bias0 = Bv[wm + am * 16 + gID];
            float bias1 = Bv[wm + am * 16 + gID + 8];
            int mm = wm + am * 16 + gID;
#pragma unroll
            for (int an = 0; an < 8; ++an) {
                int nn = wn + an * 8 + 2 * tig;
                *(__half*)(Es + nn * SROW + mm * 2)             = __float2half(acc[am][an][0] + bias0);
                *(__half*)(Es + (nn + 1) * SROW + mm * 2)       = __float2half(acc[am][an][1] + bias0);
                *(__half*)(Es + nn * SROW + (mm + 8) * 2)       = __float2half(acc[am][an][2] + bias1);
                *(__half*)(Es + (nn + 1) * SROW + (mm + 8) * 2) = __float2half(acc[am][an][3] + bias1);
            }
        }
        __syncthreads();
        __half* O = ((sel == 0) ? d_thT : d_phT) + (size_t)b * NPIX * CHALF;
#pragma unroll
        for (int e = 0; e < 8; ++e) {
            int idx = e * 256 + tid;
            int row = idx >> 4, kb = idx & 15;
            *(uint4*)(O + (size_t)(n0 + row) * CHALF + kb * 8) = *(const uint4*)(Es + row * SROW + kb * 16);
        }
    } else {
        // stage [m][n] f16 (stride 272), bias per m
#pragma unroll
        for (int am = 0; am < 2; ++am) {
            float bias0 = Bv[wm + am * 16 + gID];
            float bias1 = Bv[wm + am * 16 + gID + 8];
            int mm = wm + am * 16 + gID;
#pragma unroll
            for (int an = 0; an < 8; ++an) {
                int nn = wn + an * 8 + 2 * tig;
                *(uint32_t*)(Es + mm * SROW + nn * 2)       = pack_f16x2(acc[am][an][0] + bias0, acc[am][an][1] + bias0);
                *(uint32_t*)(Es + (mm + 8) * SROW + nn * 2) = pack_f16x2(acc[am][an][2] + bias1, acc[am][an][3] + bias1);
            }
        }
        __syncthreads();
        __half* O = d_gu + (size_t)b * CHALF * NPIX;
#pragma unroll
        for (int e = 0; e < 8; ++e) {
            int idx = e * 256 + tid;
            int row = idx >> 4, kb = idx & 15;
            *(uint4*)(O + (size_t)row * NPIX + n0 + kb * 8) = *(const uint4*)(Es + row * SROW + kb * 16);
        }
    }
}

// ============================================================
// Kernel 2: scores via mma (f16 in, f16 acc, 3 CTAs/SM).
// CTA tile 128(i) x 128(j), K=128. E -> e4m3 gmem; col sums (fp32) via shfl.
// ============================================================
__global__ __launch_bounds__(256, 3) void scores_mma_kernel()
{
    extern __shared__ __align__(16) char smem[];
    char* Asm = smem;              // 128 * 272 = 34816
    char* Bsm = smem + 34816;
    float* sums = (float*)(smem + 69632);   // [4][128] fp32 = 2KB
    const uint32_t Asb = smem_u32(Asm), Bsb = smem_u32(Bsm);

    const int tid = threadIdx.x, wid = tid >> 5, lane = tid & 31;
    const int j0 = blockIdx.x * 128, i0 = blockIdx.y * 128, b = blockIdx.z;

    const __half* Ath = d_thT + ((size_t)b * NPIX + i0) * CHALF;
    const __half* Bph = d_phT + ((size_t)b * NPIX + j0) * CHALF;

#pragma unroll
    for (int e = 0; e < 8; ++e) {
        int idx = e * 256 + tid;
        int row = idx >> 4, kb = idx & 15;
        cp16(Asb + row * SROW + kb * 16, Ath + (size_t)row * CHALF + kb * 8);
        cp16(Bsb + row * SROW + kb * 16, Bph + (size_t)row * CHALF + kb * 8);
    }
    cp_commit(); cp_wait0();
    __syncthreads();

    const int wm = (wid & 3) * 32, wn = (wid >> 2) * 64;
    const int id = lane >> 3, l7 = lane & 7;

    uint32_t acc[2][8][2];   // f16x2 accumulators
#pragma unroll
    for (int am = 0; am < 2; ++am)
#pragma unroll
        for (int an = 0; an < 8; ++an) { acc[am][an][0] = 0u; acc[am][an][1] = 0u; }

#pragma unroll
    for (int ks = 0; ks < 8; ++ks) {
        uint32_t a[2][4];
#pragma unroll
        for (int am = 0; am < 2; ++am) {
            uint32_t addr = Asb + (uint32_t)(wm + am * 16 + (id & 1) * 8 + l7) * SROW
                          + (uint32_t)(ks * 16 + (id >> 1) * 8) * 2;
            ldm_x4(a[am][0], a[am][1], a[am][2], a[am][3], addr);
        }
        uint32_t bf[8][2];
#pragma unroll
        for (int p = 0; p < 4; ++p) {
            uint32_t r0, r1, r2, r3;
            uint32_t addr = Bsb + (uint32_t)(wn + p * 16 + (id >> 1) * 8 + l7) * SROW
                          + (uint32_t)(ks * 16 + (id & 1) * 8) * 2;
            ldm_x4(r0, r1, r2, r3, addr);
            bf[p * 2][0] = r0; bf[p * 2][1] = r1;
            bf[p * 2 + 1][0] = r2; bf[p * 2 + 1][1] = r3;
        }
#pragma unroll
        for (int am = 0; am < 2; ++am)
#pragma unroll
            for (int an = 0; an < 8; ++an)
                mma_f16acc(acc[am][an], a[am], bf[an]);
    }
    __syncthreads();   // tile reads done; reuse smem as staging

    // epilogue: per-fragment exp -> stage e4m3 E (stride FROW) + running col sums
    char* Es = smem;
    const int gID = lane >> 2, tig = lane & 3;
    float s[8][2];
#pragma unroll
    for (int an = 0; an < 8; ++an) { s[an][0] = 0.f; s[an][1] = 0.f; }

#pragma unroll
    for (int am = 0; am < 2; ++am)
#pragma unroll
        for (int an = 0; an < 8; ++an) {
            float2 f0 = __half22float2(*(__half2*)&acc[am][an][0]);
            float2 f1 = __half22float2(*(__half2*)&acc[am][an][1]);
            float e0 = __expf(f0.x), e1 = __expf(f0.y);
            float e2 = __expf(f1.x), e3 = __expf(f1.y);
            int m0 = wm + am * 16, n0 = wn + an * 8 + 2 * tig;
            *(uint16_t*)(Es + (m0 + gID) * FROW + n0)     = pack_e4m3x2(e0, e1);
            *(uint16_t*)(Es + (m0 + gID + 8) * FROW + n0) = pack_e4m3x2(e2, e3);
            s[an][0] += e0 + e2;
            s[an][1] += e1 + e3;
        }

#pragma unroll
    for (int an = 0; an < 8; ++an) {
        float s0 = s[an][0], s1 = s[an][1];
        s0 += __shfl_xor_sync(0xffffffffu, s0, 4);
        s0 += __shfl_xor_sync(0xffffffffu, s0, 8);
        s0 += __shfl_xor_sync(0xffffffffu, s0, 16);
        s1 += __shfl_xor_sync(0xffffffffu, s1, 4);
        s1 += __shfl_xor_sync(0xffffffffu, s1, 8);
        s1 += __shfl_xor_sync(0xffffffffu, s1, 16);
        if (lane < 4) {
            int col = wn + an * 8 + 2 * lane;
            sums[(wid & 3) * 128 + col]     = s0;
            sums[(wid & 3) * 128 + col + 1] = s1;
        }
    }
    __syncthreads();

    // write E tile (coalesced) + den partials
    uint8_t* Eb = d_E + ((size_t)b * NPIX + i0) * NPIX + j0;
#pragma unroll
    for (int e = 0; e < 4; ++e) {
        int idx = e * 256 + tid;
        int row = idx >> 3, kb = idx & 7;
        *(uint4*)(Eb + (size_t)row * NPIX + kb * 16) = *(const uint4*)(Es + row * FROW + kb * 16);
    }
    if (tid < 128)
        d_denp[((size_t)b * 32 + blockIdx.y) * NPIX + j0 + tid]
            = sums[tid] + sums[128 + tid] + sums[256 + tid] + sums[384 + tid];
}

// ============================================================
// Kernel 3 (FUSED den reduce + g scale):
// den[j] = sum of 32 partials; gs8[b][c][j] = e4m3(gu[b][c][j] * 4096 / den[j]).
// ============================================================
__global__ __launch_bounds__(256) void denscale_kernel()
{
    const int j = blockIdx.x * 1024 + threadIdx.x * 4;
    const int b = blockIdx.y;

    float4 s = make_float4(0.f, 0.f, 0.f, 0.f);
#pragma unroll
    for (int t = 0; t < 32; ++t) {
        float4 v = *(const float4*)&d_denp[((size_t)b * 32 + t) * NPIX + j];
        s.x += v.x; s.y += v.y; s.z += v.z; s.w += v.w;
    }
    float4 inv = make_float4(4096.f / s.x, 4096.f / s.y, 4096.f / s.z, 4096.f / s.w);

    const __half* gu = d_gu  + (size_t)b * CHALF * NPIX + j;
    uint8_t*      gs = d_gs8 + (size_t)b * CHALF * NPIX + j;
#pragma unroll 4
    for (int c = 0; c < CHALF; ++c) {
        uint2 gv = *(const uint2*)(gu + (size_t)c * NPIX);
        float2 f0 = __half22float2(*(__half2*)&gv.x);
        float2 f1 = __half22float2(*(__half2*)&gv.y);
        uint32_t w = (uint32_t)pack_e4m3x2(f0.x * inv.x, f0.y * inv.y)
                   | ((uint32_t)pack_e4m3x2(f1.x * inv.z, f1.y * inv.w) << 16);
        *(uint32_t*)(gs + (size_t)c * NPIX) = w;
    }
}

// ============================================================
// Kernel 4 (FUSED y + out): y via fp8 mma (3-stage pipeline), then
// out = w4*y + b4 + x in-CTA.
// smem: 3 stages x 36864 = 110592. Post-loop: y @0 (34816), w4 @36864 (+69632).
// ============================================================
__global__ __launch_bounds__(256) void y_out_kernel(
    const float* __restrict__ x, const float* __restrict__ b4, float* __restrict__ out)
{
    extern __shared__ __align__(16) char smem[];
    const uint32_t sb = smem_u32(smem);

    const int tid = threadIdx.x, wid = tid >> 5, lane = tid & 31;
    const int i0 = blockIdx.x * 128, b = blockIdx.y;

    const uint8_t* Ebase = d_E   + ((size_t)b * NPIX + i0) * NPIX;
    const uint8_t* Gbase = d_gs8 + (size_t)b * CHALF * NPIX;

    const int wm = (wid & 3) * 32, wn = (wid >> 2) * 64;
    const int id = lane >> 3, l7 = lane & 7;

    float accf[2][8][4];
#pragma unroll
    for (int am = 0; am < 2; ++am)
#pragma unroll
        for (int an = 0; an < 8; ++an)
#pragma unroll
            for (int q = 0; q < 4; ++q) accf[am][an][q] = 0.f;

    auto issue_chunk = [&](int c) {
        uint32_t st = sb + (uint32_t)(c % 3) * 36864;
        size_t k0 = (size_t)c * 128;
#pragma unroll
        for (int e = 0; e < 4; ++e) {
            int idx = e * 256 + tid;
            int row = idx >> 3, kb = idx & 7;
            cp16(st + row * FROW + kb * 16,         Ebase + (size_t)row * NPIX + k0 + kb * 16);
            cp16(st + 18432 + row * FROW + kb * 16, Gbase + (size_t)row * NPIX + k0 + kb * 16);
        }
    };

    issue_chunk(0); cp_commit();
    issue_chunk(1); cp_commit();

    for (int c = 0; c < 32; ++c) {
        if (c < 31) cp_wait1(); else cp_wait0();
        __syncthreads();
        if (c + 2 < 32) { issue_chunk(c + 2); cp_commit(); }

        uint32_t Ab = sb + (uint32_t)(c % 3) * 36864;
        uint32_t Bb = Ab + 18432;
#pragma unroll
        for (int ks = 0; ks < 4; ++ks) {            // k32 steps over 128
            uint32_t a[2][4];
#pragma unroll
            for (int am = 0; am < 2; ++am) {
                uint32_t addr = Ab + (uint32_t)(wm + am * 16 + (id & 1) * 8 + l7) * FROW
                              + (uint32_t)(ks * 32 + (id >> 1) * 16);
                ldm_x4(a[am][0], a[am][1], a[am][2], a[am][3], addr);
            }
            uint32_t bf[8][2];
#pragma unroll
            for (int p = 0; p < 4; ++p) {
                uint32_t r0, r1, r2, r3;
                uint32_t addr = Bb + (uint32_t)(wn + p * 16 + (id >> 1) * 8 + l7) * FROW
                              + (uint32_t)(ks * 32 + (id & 1) * 16);
                ldm_x4(r0, r1, r2, r3, addr);
                bf[p * 2][0] = r0; bf[p * 2][1] = r1;
                bf[p * 2 + 1][0] = r2; bf[p * 2 + 1][1] = r3;
            }
#pragma unroll
            for (int am = 0; am < 2; ++am)
#pragma unroll
                for (int an = 0; an < 8; ++an)
                    mma_e4m3(accf[am][an], a[am], bf[an]);
        }
    }
    __syncthreads();   // mainloop smem free

    // stage y = accf * (1/4096) as f16 [m=i][n=c] at smem+0;
    // concurrently cp.async w4 [256][128] f16 into smem+36864
    const float S = 1.f / 4096.f;
    char* Ys = smem;
    const uint32_t Wb = sb + 36864;
    const int gID = lane >> 2, tig = lane & 3;
#pragma unroll
    for (int e = 0; e < 16; ++e) {
        int idx = e * 256 + tid;
        int row = idx >> 4, kb = idx & 15;
        cp16(Wb + row * SROW + kb * 16, d_w4b + (size_t)row * CHALF + kb * 8);
    }
    cp_commit();
#pragma unroll
    for (int am = 0; am < 2; ++am)
#pragma unroll
        for (int an = 0; an < 8; ++an) {
            int mm = wm + am * 16 + gID, nn = wn + an * 8 + 2 * tig;
            *(uint32_t*)(Ys + mm * SROW + nn * 2)       = pack_f16x2(accf[am][an][0] * S, accf[am][an][1] * S);
            *(uint32_t*)(Ys + (mm + 8) * SROW + nn * 2) = pack_f16x2(accf[am][an][2] * S, accf[am][an][3] * S);
        }
    cp_wait0();
    __syncthreads();

    // out GEMM: two o-halves of 128. A = w4 rows (o), B = y rows (i), K = c.
    const uint32_t Yb = sb;
    for (int h = 0; h < 2; ++h) {
        int o0 = h * 128;
        float acc2[2][8][4];
#pragma unroll
        for (int am = 0; am < 2; ++am)
#pragma unroll
            for (int an = 0; an < 8; ++an)
#pragma unroll
                for (int q = 0; q < 4; ++q) acc2[am][an][q] = 0.f;

#pragma unroll
        for (int ks = 0; ks < 8; ++ks) {
            uint32_t a[2][4];
#pragma unroll
            for (int am = 0; am < 2; ++am) {
                uint32_t addr = Wb + (uint32_t)(o0 + wm + am * 16 + (id & 1) * 8 + l7) * SROW
                              + (uint32_t)(ks * 16 + (id >> 1) * 8) * 2;
                ldm_x4(a[am][0], a[am][1], a[am][2], a[am][3], addr);
            }
            uint32_t bf[8][2];
#pragma unroll
            for (int p = 0; p < 4; ++p) {
                uint32_t r0, r1, r2, r3;
                uint32_t addr = Yb + (uint32_t)(wn + p * 16 + (id >> 1) * 8 + l7) * SROW
                              + (uint32_t)(ks * 16 + (id & 1) * 8) * 2;
                ldm_x4(r0, r1, r2, r3, addr);
                bf[p * 2][0] = r0; bf[p * 2][1] = r1;
                bf[p * 2 + 1][0] = r2; bf[p * 2 + 1][1] = r3;
            }
#pragma unroll
            for (int am = 0; am < 2; ++am)
#pragma unroll
                for (int an = 0; an < 8; ++an)
                    mma_f16(acc2[am][an], a[am], bf[an]);
        }

#pragma unroll
        for (int am = 0; am < 2; ++am) {
            int mo0 = o0 + wm + am * 16 + gID;
            int mo1 = mo0 + 8;
            float bias0 = b4[mo0], bias1 = b4[mo1];
#pragma unroll
            for (int an = 0; an < 8; ++an) {
                int nn = i0 + wn + an * 8 + 2 * tig;
                size_t off0 = ((size_t)b * CDIM + mo0) * NPIX + nn;
                size_t off1 = ((size_t)b * CDIM + mo1) * NPIX + nn;
                float2 x0 = *(const float2*)&x[off0];
                float2 x1 = *(const float2*)&x[off1];
                *(float2*)&out[off0] = make_float2(acc2[am][an][0] + bias0 + x0.x,
                                                   acc2[am][an][1] + bias0 + x0.y);
                *(float2*)&out[off1] = make_float2(acc2[am][an][2] + bias1 + x1.x,
                                                   acc2[am][an][3] + bias1 + x1.y);
            }
        }
    }
}

// ============================================================
extern "C" void kernel_launch(void* const* d_in, const int* in_sizes, int n_in,
                              void* d_out, int out_size)
{
    const float* x  = (const float*)d_in[0];
    const float* w1 = (const float*)d_in[1];
    const float* b1 = (const float*)d_in[2];
    const float* w2 = (const float*)d_in[3];
    const float* b2 = (const float*)d_in[4];
    const float* w3 = (const float*)d_in[5];
    const float* b3 = (const float*)d_in[6];
    const float* w4 = (const float*)d_in[7];
    const float* b4 = (const float*)d_in[8];
    float* out = (float*)d_out;

    const int P_SMEM  = 2 * 128 * PROW;            // 135168
    const int SC_SMEM = 2 * 128 * SROW + 2048;     // 71680 (3 CTAs/SM)
    const int Y_SMEM  = 3 * 2 * 128 * FROW;        // 110592
    cudaFuncSetAttribute(proj_mma_kernel,   cudaFuncAttributeMaxDynamicSharedMemorySize, P_SMEM);
    cudaFuncSetAttribute(scores_mma_kernel, cudaFuncAttributeMaxDynamicSharedMemorySize, SC_SMEM);
    cudaFuncSetAttribute(y_out_kernel,      cudaFuncAttributeMaxDynamicSharedMemorySize, Y_SMEM);

    wconv_kernel     <<<512, 256>>>(w1, w2, w3, w4);
    xT_kernel        <<<dim3(NPIX / 32, CDIM / 32, BATCH), dim3(32, 8)>>>(x);
    proj_mma_kernel  <<<dim3(NPIX / 128, 3, BATCH), 256, P_SMEM>>>(b1, b2, b3);
    scores_mma_kernel<<<dim3(NPIX / 128, NPIX / 128, BATCH), 256, SC_SMEM>>>();
    denscale_kernel  <<<dim3(NPIX / 1024, BATCH), 256>>>();
    y_out_kernel     <<<dim3(NPIX / 128, BATCH), 256, Y_SMEM>>>(x, b4, out);
}

// round 14
// speedup vs baseline: 1.4365x; 1.4365x over previous
#include <cuda_runtime.h>
#include <cuda_fp16.h>
#include <math.h>
#include <stdint.h>

#define BATCH 4
#define CDIM  256
#define CHALF 128
#define NPIX  4096

// ---- scratch (device globals; no dynamic allocation allowed) ----
__device__ __half d_wb [3 * CHALF * CDIM];            // w1|w2|w3 f16 [3][128][256]
__device__ __half d_w4b[CDIM * CHALF];                // w4 f16 [256][128]
__device__ __half d_xT [BATCH * NPIX * CDIM];         // x^T [b][n][c] f16
__device__ __half d_thT[BATCH * NPIX * CHALF];        // theta^T [b][i][c] f16
__device__ __half d_phT[BATCH * NPIX * CHALF];        // phi^T   [b][j][c] f16
__device__ __half d_gu [BATCH * CHALF * NPIX];        // g unscaled [b][c][j] f16
__device__ __align__(128) uint8_t d_gs8[BATCH * CHALF * NPIX];  // g*4096/den e4m3 [b][c][j]
__device__ float  d_denp[BATCH * 32 * NPIX];
__device__ __align__(128) uint8_t d_E[(size_t)BATCH * NPIX * NPIX]; // exp(scores) e4m3, 64 MB

// ================= helpers =================
__device__ __forceinline__ uint32_t smem_u32(const void* p) {
    uint32_t a;
    asm("{ .reg .u64 t; cvta.to.shared.u64 t, %1; cvt.u32.u64 %0, t; }" : "=r"(a) : "l"(p));
    return a;
}
__device__ __forceinline__ uint32_t pack_f16x2(float lo, float hi) {
    __half2 h = __floats2half2_rn(lo, hi);
    return *(uint32_t*)&h;
}
__device__ __forceinline__ uint16_t pack_e4m3x2(float lo, float hi) {
    uint16_t r;
    asm("cvt.rn.satfinite.e4m3x2.f32 %0, %1, %2;" : "=h"(r) : "f"(hi), "f"(lo));
    return r;
}
__device__ __forceinline__ void ldm_x4(uint32_t& r0, uint32_t& r1, uint32_t& r2, uint32_t& r3,
                                       uint32_t addr) {
    asm volatile("ldmatrix.sync.aligned.m8n8.x4.shared.b16 {%0,%1,%2,%3}, [%4];"
                 : "=r"(r0), "=r"(r1), "=r"(r2), "=r"(r3) : "r"(addr));
}
__device__ __forceinline__ void mma_f16(float* c, const uint32_t* a, const uint32_t* b) {
    asm volatile(
        "mma.sync.aligned.m16n8k16.row.col.f32.f16.f16.f32 "
        "{%0,%1,%2,%3}, {%4,%5,%6,%7}, {%8,%9}, {%0,%1,%2,%3};"
        : "+f"(c[0]), "+f"(c[1]), "+f"(c[2]), "+f"(c[3])
        : "r"(a[0]), "r"(a[1]), "r"(a[2]), "r"(a[3]), "r"(b[0]), "r"(b[1]));
}
__device__ __forceinline__ void mma_f16acc(uint32_t* c, const uint32_t* a, const uint32_t* b) {
    asm volatile(
        "mma.sync.aligned.m16n8k16.row.col.f16.f16.f16.f16 "
        "{%0,%1}, {%2,%3,%4,%5}, {%6,%7}, {%0,%1};"
        : "+r"(c[0]), "+r"(c[1])
        : "r"(a[0]), "r"(a[1]), "r"(a[2]), "r"(a[3]), "r"(b[0]), "r"(b[1]));
}
__device__ __forceinline__ void mma_e4m3(float* c, const uint32_t* a, const uint32_t* b) {
    asm volatile(
        "mma.sync.aligned.m16n8k32.row.col.f32.e4m3.e4m3.f32 "
        "{%0,%1,%2,%3}, {%4,%5,%6,%7}, {%8,%9}, {%0,%1,%2,%3};"
        : "+f"(c[0]), "+f"(c[1]), "+f"(c[2]), "+f"(c[3])
        : "r"(a[0]), "r"(a[1]), "r"(a[2]), "r"(a[3]), "r"(b[0]), "r"(b[1]));
}
__device__ __forceinline__ void cp16(uint32_t dst, const void* src) {
    asm volatile("cp.async.cg.shared.global [%0], [%1], 16;" :: "r"(dst), "l"(src) : "memory");
}
__device__ __forceinline__ void cp_commit() { asm volatile("cp.async.commit_group;" ::: "memory"); }
__device__ __forceinline__ void cp_wait0()  { asm volatile("cp.async.wait_group 0;" ::: "memory"); }
__device__ __forceinline__ void cp_wait1()  { asm volatile("cp.async.wait_group 1;" ::: "memory"); }

#define SROW 272   // 128 f16 row + 16B pad
#define PROW 528   // 256 f16 row + 16B pad
#define FROW 144   // 128 fp8 row + 16B pad

// ============================================================
// Kernel 0a: weight convert to f16
// ============================================================
__global__ void wconv_kernel(const float* __restrict__ w1, const float* __restrict__ w2,
                             const float* __restrict__ w3, const float* __restrict__ w4)
{
    int idx = blockIdx.x * 256 + threadIdx.x;   // 131072 total
    if (idx < 98304) {
        int sel = idx >> 15, r = idx & 32767;
        const float* W = (sel == 0) ? w1 : (sel == 1) ? w2 : w3;
        d_wb[idx] = __float2half(W[r]);
    } else {
        int r = idx - 98304;
        d_w4b[r] = __float2half(w4[r]);
    }
}

// ============================================================
// Kernel 0b: x transpose-convert: [b][c][n] fp32 -> [b][n][c] f16
// ============================================================
__global__ void xT_kernel(const float* __restrict__ x)
{
    __shared__ float t[32][33];
    const int n0 = blockIdx.x * 32, c0 = blockIdx.y * 32, b = blockIdx.z;
    const float* xb = x + ((size_t)b * CDIM + c0) * NPIX + n0;
    for (int r = threadIdx.y; r < 32; r += 8)
        t[r][threadIdx.x] = xb[(size_t)r * NPIX + threadIdx.x];
    __syncthreads();
    __half* o = d_xT + ((size_t)b * NPIX + n0) * CDIM + c0;
    for (int r = threadIdx.y; r < 32; r += 8)
        o[(size_t)r * CDIM + threadIdx.x] = __float2half(t[threadIdx.x][r]);
}

// ============================================================
// Kernel 1: proj via mma (f16 in, f32 acc). M=128, N=128, K=256.
// sel 0/1 -> thT/phT f16 [n][m]; sel 2 -> gu f16 [m][n].
// ============================================================
__global__ __launch_bounds__(256) void proj_mma_kernel(
    const float* __restrict__ b1, const float* __restrict__ b2, const float* __restrict__ b3)
{
    extern __shared__ __align__(16) char smem[];
    char* Asm = smem;               // 128*528 = 67584
    char* Bsm = smem + 67584;
    const uint32_t Asb = smem_u32(Asm), Bsb = smem_u32(Bsm);

    const int tid = threadIdx.x, wid = tid >> 5, lane = tid & 31;
    const int n0 = blockIdx.x * 128, sel = blockIdx.y, b = blockIdx.z;
    const float* Bv = (sel == 0) ? b1 : (sel == 1) ? b2 : b3;

    const __half* W = d_wb + (size_t)sel * CHALF * CDIM;
    const __half* X = d_xT + ((size_t)b * NPIX + n0) * CDIM;

#pragma unroll
    for (int e = 0; e < 16; ++e) {
        int idx = e * 256 + tid;
        int row = idx >> 5, kb = idx & 31;
        cp16(Asb + row * PROW + kb * 16, W + (size_t)row * CDIM + kb * 8);
        cp16(Bsb + row * PROW + kb * 16, X + (size_t)row * CDIM + kb * 8);
    }
    cp_commit(); cp_wait0();
    __syncthreads();

    const int wm = (wid & 3) * 32, wn = (wid >> 2) * 64;
    const int id = lane >> 3, l7 = lane & 7;

    float acc[2][8][4];
#pragma unroll
    for (int am = 0; am < 2; ++am)
#pragma unroll
        for (int an = 0; an < 8; ++an)
#pragma unroll
            for (int q = 0; q < 4; ++q) acc[am][an][q] = 0.f;

#pragma unroll
    for (int ks = 0; ks < 16; ++ks) {
        uint32_t a[2][4];
#pragma unroll
        for (int am = 0; am < 2; ++am) {
            uint32_t addr = Asb + (uint32_t)(wm + am * 16 + (id & 1) * 8 + l7) * PROW
                          + (uint32_t)(ks * 16 + (id >> 1) * 8) * 2;
            ldm_x4(a[am][0], a[am][1], a[am][2], a[am][3], addr);
        }
        uint32_t bf[8][2];
#pragma unroll
        for (int p = 0; p < 4; ++p) {
            uint32_t r0, r1, r2, r3;
            uint32_t addr = Bsb + (uint32_t)(wn + p * 16 + (id >> 1) * 8 + l7) * PROW
                          + (uint32_t)(ks * 16 + (id & 1) * 8) * 2;
            ldm_x4(r0, r1, r2, r3, addr);
            bf[p * 2][0] = r0; bf[p * 2][1] = r1;
            bf[p * 2 + 1][0] = r2; bf[p * 2 + 1][1] = r3;
        }
#pragma unroll
        for (int am = 0; am < 2; ++am)
#pragma unroll
            for (int an = 0; an < 8; ++an)
                mma_f16(acc[am][an], a[am], bf[an]);
    }
    __syncthreads();

    char* Es = smem;
    const int gID = lane >> 2, tig = lane & 3;

    if (sel < 2) {
        // stage transposed [n][m] f16 (stride 272), bias per m
#pragma unroll
        for (int am = 0; am < 2; ++am) {
            float bias0 = Bv[wm + am * 16 + gID];
            float bias1 = Bv[wm + am * 16 + gID + 8];
            int mm = wm + am * 16 + gID;
#pragma unroll
            for (int an = 0; an < 8; ++an) {
                int nn = wn + an * 8 + 2 * tig;
                *(__half*)(Es + nn * SROW + mm * 2)             = __float2half(acc[am][an][0] + bias0);
                *(__half*)(Es + (nn + 1) * SROW + mm * 2)       = __float2half(acc[am][an][1] + bias0);
                *(__half*)(Es + nn * SROW + (mm + 8) * 2)       = __float2half(acc[am][an][2] + bias1);
                *(__half*)(Es + (nn + 1) * SROW + (mm + 8) * 2) = __float2half(acc[am][an][3] + bias1);
            }
        }
        __syncthreads();
        __half* O = ((sel == 0) ? d_thT : d_phT) + (size_t)b * NPIX * CHALF;
#pragma unroll
        for (int e = 0; e < 8; ++e) {
            int idx = e * 256 + tid;
            int row = idx >> 4, kb = idx & 15;
            *(uint4*)(O + (size_t)(n0 + row) * CHALF + kb * 8) = *(const uint4*)(Es + row * SROW + kb * 16);
        }
    } else {
        // stage [m][n] f16 (stride 272), bias per m
#pragma unroll
        for (int am = 0; am < 2; ++am) {
            float bias0 = Bv[wm + am * 16 + gID];
            float bias1 = Bv[wm + am * 16 + gID + 8];
            int mm = wm + am * 16 + gID;
#pragma unroll
            for (int an = 0; an < 8; ++an) {
                int nn = wn + an * 8 + 2 * tig;
                *(uint32_t*)(Es + mm * SROW + nn * 2)       = pack_f16x2(acc[am][an][0] + bias0, acc[am][an][1] + bias0);
                *(uint32_t*)(Es + (mm + 8) * SROW + nn * 2) = pack_f16x2(acc[am][an][2] + bias1, acc[am][an][3] + bias1);
            }
        }
        __syncthreads();
        __half* O = d_gu + (size_t)b * CHALF * NPIX;
#pragma unroll
        for (int e = 0; e < 8; ++e) {
            int idx = e * 256 + tid;
            int row = idx >> 4, kb = idx & 15;
            *(uint4*)(O + (size_t)row * NPIX + n0 + kb * 8) = *(const uint4*)(Es + row * SROW + kb * 16);
        }
    }
}

// ============================================================
// Kernel 2: scores via mma (f16 in, f16 acc, 3 CTAs/SM).
// CTA tile 128(i) x 128(j), K=128. E -> e4m3 gmem; col sums (fp32) via shfl.
// ============================================================
__global__ __launch_bounds__(256, 3) void scores_mma_kernel()
{
    extern __shared__ __align__(16) char smem[];
    char* Asm = smem;              // 128 * 272 = 34816
    char* Bsm = smem + 34816;
    float* sums = (float*)(smem + 69632);   // [4][128] fp32 = 2KB
    const uint32_t Asb = smem_u32(Asm), Bsb = smem_u32(Bsm);

    const int tid = threadIdx.x, wid = tid >> 5, lane = tid & 31;
    const int j0 = blockIdx.x * 128, i0 = blockIdx.y * 128, b = blockIdx.z;

    const __half* Ath = d_thT + ((size_t)b * NPIX + i0) * CHALF;
    const __half* Bph = d_phT + ((size_t)b * NPIX + j0) * CHALF;

#pragma unroll
    for (int e = 0; e < 8; ++e) {
        int idx = e * 256 + tid;
        int row = idx >> 4, kb = idx & 15;
        cp16(Asb + row * SROW + kb * 16, Ath + (size_t)row * CHALF + kb * 8);
        cp16(Bsb + row * SROW + kb * 16, Bph + (size_t)row * CHALF + kb * 8);
    }
    cp_commit(); cp_wait0();
    __syncthreads();

    const int wm = (wid & 3) * 32, wn = (wid >> 2) * 64;
    const int id = lane >> 3, l7 = lane & 7;

    uint32_t acc[2][8][2];   // f16x2 accumulators
#pragma unroll
    for (int am = 0; am < 2; ++am)
#pragma unroll
        for (int an = 0; an < 8; ++an) { acc[am][an][0] = 0u; acc[am][an][1] = 0u; }

#pragma unroll
    for (int ks = 0; ks < 8; ++ks) {
        uint32_t a[2][4];
#pragma unroll
        for (int am = 0; am < 2; ++am) {
            uint32_t addr = Asb + (uint32_t)(wm + am * 16 + (id & 1) * 8 + l7) * SROW
                          + (uint32_t)(ks * 16 + (id >> 1) * 8) * 2;
            ldm_x4(a[am][0], a[am][1], a[am][2], a[am][3], addr);
        }
        uint32_t bf[8][2];
#pragma unroll
        for (int p = 0; p < 4; ++p) {
            uint32_t r0, r1, r2, r3;
            uint32_t addr = Bsb + (uint32_t)(wn + p * 16 + (id >> 1) * 8 + l7) * SROW
                          + (uint32_t)(ks * 16 + (id & 1) * 8) * 2;
            ldm_x4(r0, r1, r2, r3, addr);
            bf[p * 2][0] = r0; bf[p * 2][1] = r1;
            bf[p * 2 + 1][0] = r2; bf[p * 2 + 1][1] = r3;
        }
#pragma unroll
        for (int am = 0; am < 2; ++am)
#pragma unroll
            for (int an = 0; an < 8; ++an)
                mma_f16acc(acc[am][an], a[am], bf[an]);
    }
    __syncthreads();   // tile reads done; reuse smem as staging

    // epilogue: per-fragment exp -> stage e4m3 E (stride FROW) + running col sums
    char* Es = smem;
    const int gID = lane >> 2, tig = lane & 3;
    float s[8][2];
#pragma unroll
    for (int an = 0; an < 8; ++an) { s[an][0] = 0.f; s[an][1] = 0.f; }

#pragma unroll
    for (int am = 0; am < 2; ++am)
#pragma unroll
        for (int an = 0; an < 8; ++an) {
            float2 f0 = __half22float2(*(__half2*)&acc[am][an][0]);
            float2 f1 = __half22float2(*(__half2*)&acc[am][an][1]);
            float e0 = __expf(f0.x), e1 = __expf(f0.y);
            float e2 = __expf(f1.x), e3 = __expf(f1.y);
            int m0 = wm + am * 16, n0 = wn + an * 8 + 2 * tig;
            *(uint16_t*)(Es + (m0 + gID) * FROW + n0)     = pack_e4m3x2(e0, e1);
            *(uint16_t*)(Es + (m0 + gID + 8) * FROW + n0) = pack_e4m3x2(e2, e3);
            s[an][0] += e0 + e2;
            s[an][1] += e1 + e3;
        }

#pragma unroll
    for (int an = 0; an < 8; ++an) {
        float s0 = s[an][0], s1 = s[an][1];
        s0 += __shfl_xor_sync(0xffffffffu, s0, 4);
        s0 += __shfl_xor_sync(0xffffffffu, s0, 8);
        s0 += __shfl_xor_sync(0xffffffffu, s0, 16);
        s1 += __shfl_xor_sync(0xffffffffu, s1, 4);
        s1 += __shfl_xor_sync(0xffffffffu, s1, 8);
        s1 += __shfl_xor_sync(0xffffffffu, s1, 16);
        if (lane < 4) {
            int col = wn + an * 8 + 2 * lane;
            sums[(wid & 3) * 128 + col]     = s0;
            sums[(wid & 3) * 128 + col + 1] = s1;
        }
    }
    __syncthreads();

    // write E tile (coalesced) + den partials
    uint8_t* Eb = d_E + ((size_t)b * NPIX + i0) * NPIX + j0;
#pragma unroll
    for (int e = 0; e < 4; ++e) {
        int idx = e * 256 + tid;
        int row = idx >> 3, kb = idx & 7;
        *(uint4*)(Eb + (size_t)row * NPIX + kb * 16) = *(const uint4*)(Es + row * FROW + kb * 16);
    }
    if (tid < 128)
        d_denp[((size_t)b * 32 + blockIdx.y) * NPIX + j0 + tid]
            = sums[tid] + sums[128 + tid] + sums[256 + tid] + sums[384 + tid];
}

// ============================================================
// Kernel 3 (FUSED den reduce + g scale):
// den[j] = sum of 32 partials; gs8[b][c][j] = e4m3(gu[b][c][j] * 4096 / den[j]).
// ============================================================
__global__ __launch_bounds__(256) void denscale_kernel()
{
    const int j = blockIdx.x * 1024 + threadIdx.x * 4;
    const int b = blockIdx.y;

    float4 s = make_float4(0.f, 0.f, 0.f, 0.f);
#pragma unroll
    for (int t = 0; t < 32; ++t) {
        float4 v = *(const float4*)&d_denp[((size_t)b * 32 + t) * NPIX + j];
        s.x += v.x; s.y += v.y; s.z += v.z; s.w += v.w;
    }
    float4 inv = make_float4(4096.f / s.x, 4096.f / s.y, 4096.f / s.z, 4096.f / s.w);

    const __half* gu = d_gu  + (size_t)b * CHALF * NPIX + j;
    uint8_t*      gs = d_gs8 + (size_t)b * CHALF * NPIX + j;
#pragma unroll 4
    for (int c = 0; c < CHALF; ++c) {
        uint2 gv = *(const uint2*)(gu + (size_t)c * NPIX);
        float2 f0 = __half22float2(*(__half2*)&gv.x);
        float2 f1 = __half22float2(*(__half2*)&gv.y);
        uint32_t w = (uint32_t)pack_e4m3x2(f0.x * inv.x, f0.y * inv.y)
                   | ((uint32_t)pack_e4m3x2(f1.x * inv.z, f1.y * inv.w) << 16);
        *(uint32_t*)(gs + (size_t)c * NPIX) = w;
    }
}

// ============================================================
// Kernel 4 (FUSED y + out): y via fp8 mma (3-stage pipeline), then
// out = w4*y + b4 + x in-CTA.
// smem: 3 stages x 36864 = 110592. Post-loop: y @0 (34816), w4 @36864 (+69632).
// ============================================================
__global__ __launch_bounds__(256) void y_out_kernel(
    const float* __restrict__ x, const float* __restrict__ b4, float* __restrict__ out)
{
    extern __shared__ __align__(16) char smem[];
    const uint32_t sb = smem_u32(smem);

    const int tid = threadIdx.x, wid = tid >> 5, lane = tid & 31;
    const int i0 = blockIdx.x * 128, b = blockIdx.y;

    const uint8_t* Ebase = d_E   + ((size_t)b * NPIX + i0) * NPIX;
    const uint8_t* Gbase = d_gs8 + (size_t)b * CHALF * NPIX;

    const int wm = (wid & 3) * 32, wn = (wid >> 2) * 64;
    const int id = lane >> 3, l7 = lane & 7;

    float accf[2][8][4];
#pragma unroll
    for (int am = 0; am < 2; ++am)
#pragma unroll
        for (int an = 0; an < 8; ++an)
#pragma unroll
            for (int q = 0; q < 4; ++q) accf[am][an][q] = 0.f;

    auto issue_chunk = [&](int c) {
        uint32_t st = sb + (uint32_t)(c % 3) * 36864;
        size_t k0 = (size_t)c * 128;
#pragma unroll
        for (int e = 0; e < 4; ++e) {
            int idx = e * 256 + tid;
            int row = idx >> 3, kb = idx & 7;
            cp16(st + row * FROW + kb * 16,         Ebase + (size_t)row * NPIX + k0 + kb * 16);
            cp16(st + 18432 + row * FROW + kb * 16, Gbase + (size_t)row * NPIX + k0 + kb * 16);
        }
    };

    issue_chunk(0); cp_commit();
    issue_chunk(1); cp_commit();

    for (int c = 0; c < 32; ++c) {
        if (c < 31) cp_wait1(); else cp_wait0();
        __syncthreads();
        if (c + 2 < 32) { issue_chunk(c + 2); cp_commit(); }

        uint32_t Ab = sb + (uint32_t)(c % 3) * 36864;
        uint32_t Bb = Ab + 18432;
#pragma unroll
        for (int ks = 0; ks < 4; ++ks) {            // k32 steps over 128
            uint32_t a[2][4];
#pragma unroll
            for (int am = 0; am < 2; ++am) {
                uint32_t addr = Ab + (uint32_t)(wm + am * 16 + (id & 1) * 8 + l7) * FROW
                              + (uint32_t)(ks * 32 + (id >> 1) * 16);
                ldm_x4(a[am][0], a[am][1], a[am][2], a[am][3], addr);
            }
            uint32_t bf[8][2];
#pragma unroll
            for (int p = 0; p < 4; ++p) {
                uint32_t r0, r1, r2, r3;
                uint32_t addr = Bb + (uint32_t)(wn + p * 16 + (id >> 1) * 8 + l7) * FROW
                              + (uint32_t)(ks * 32 + (id & 1) * 16);
                ldm_x4(r0, r1, r2, r3, addr);
                bf[p * 2][0] = r0; bf[p * 2][1] = r1;
                bf[p * 2 + 1][0] = r2; bf[p * 2 + 1][1] = r3;
            }
#pragma unroll
            for (int am = 0; am < 2; ++am)
#pragma unroll
                for (int an = 0; an < 8; ++an)
                    mma_e4m3(accf[am][an], a[am], bf[an]);
        }
    }
    __syncthreads();   // mainloop smem free

    // stage y = accf * (1/4096) as f16 [m=i][n=c] at smem+0;
    // concurrently cp.async w4 [256][128] f16 into smem+36864
    const float S = 1.f / 4096.f;
    char* Ys = smem;
    const uint32_t Wb = sb + 36864;
    const int gID = lane >> 2, tig = lane & 3;
#pragma unroll
    for (int e = 0; e < 16; ++e) {
        int idx = e * 256 + tid;
        int row = idx >> 4, kb = idx & 15;
        cp16(Wb + row * SROW + kb * 16, d_w4b + (size_t)row * CHALF + kb * 8);
    }
    cp_commit();
#pragma unroll
    for (int am = 0; am < 2; ++am)
#pragma unroll
        for (int an = 0; an < 8; ++an) {
            int mm = wm + am * 16 + gID, nn = wn + an * 8 + 2 * tig;
            *(uint32_t*)(Ys + mm * SROW + nn * 2)       = pack_f16x2(accf[am][an][0] * S, accf[am][an][1] * S);
            *(uint32_t*)(Ys + (mm + 8) * SROW + nn * 2) = pack_f16x2(accf[am][an][2] * S, accf[am][an][3] * S);
        }
    cp_wait0();
    __syncthreads();

    // out GEMM: two o-halves of 128. A = w4 rows (o), B = y rows (i), K = c.
    const uint32_t Yb = sb;
    for (int h = 0; h < 2; ++h) {
        int o0 = h * 128;
        float acc2[2][8][4];
#pragma unroll
        for (int am = 0; am < 2; ++am)
#pragma unroll
            for (int an = 0; an < 8; ++an)
#pragma unroll
                for (int q = 0; q < 4; ++q) acc2[am][an][q] = 0.f;

#pragma unroll
        for (int ks = 0; ks < 8; ++ks) {
            uint32_t a[2][4];
#pragma unroll
            for (int am = 0; am < 2; ++am) {
                uint32_t addr = Wb + (uint32_t)(o0 + wm + am * 16 + (id & 1) * 8 + l7) * SROW
                              + (uint32_t)(ks * 16 + (id >> 1) * 8) * 2;
                ldm_x4(a[am][0], a[am][1], a[am][2], a[am][3], addr);
            }
            uint32_t bf[8][2];
#pragma unroll
            for (int p = 0; p < 4; ++p) {
                uint32_t r0, r1, r2, r3;
                uint32_t addr = Yb + (uint32_t)(wn + p * 16 + (id >> 1) * 8 + l7) * SROW
                              + (uint32_t)(ks * 16 + (id & 1) * 8) * 2;
                ldm_x4(r0, r1, r2, r3, addr);
                bf[p * 2][0] = r0; bf[p * 2][1] = r1;
                bf[p * 2 + 1][0] = r2; bf[p * 2 + 1][1] = r3;
            }
#pragma unroll
            for (int am = 0; am < 2; ++am)
#pragma unroll
                for (int an = 0; an < 8; ++an)
                    mma_f16(acc2[am][an], a[am], bf[an]);
        }

#pragma unroll
        for (int am = 0; am < 2; ++am) {
            int mo0 = o0 + wm + am * 16 + gID;
            int mo1 = mo0 + 8;
            float bias0 = b4[mo0], bias1 = b4[mo1];
#pragma unroll
            for (int an = 0; an < 8; ++an) {
                int nn = i0 + wn + an * 8 + 2 * tig;
                size_t off0 = ((size_t)b * CDIM + mo0) * NPIX + nn;
                size_t off1 = ((size_t)b * CDIM + mo1) * NPIX + nn;
                float2 x0 = *(const float2*)&x[off0];
                float2 x1 = *(const float2*)&x[off1];
                *(float2*)&out[off0] = make_float2(acc2[am][an][0] + bias0 + x0.x,
                                                   acc2[am][an][1] + bias0 + x0.y);
                *(float2*)&out[off1] = make_float2(acc2[am][an][2] + bias1 + x1.x,
                                                   acc2[am][an][3] + bias1 + x1.y);
            }
        }
    }
}

// ============================================================
extern "C" void kernel_launch(void* const* d_in, const int* in_sizes, int n_in,
                              void* d_out, int out_size)
{
    const float* x  = (const float*)d_in[0];
    const float* w1 = (const float*)d_in[1];
    const float* b1 = (const float*)d_in[2];
    const float* w2 = (const float*)d_in[3];
    const float* b2 = (const float*)d_in[4];
    const float* w3 = (const float*)d_in[5];
    const float* b3 = (const float*)d_in[6];
    const float* w4 = (const float*)d_in[7];
    const float* b4 = (const float*)d_in[8];
    float* out = (float*)d_out;

    const int P_SMEM  = 2 * 128 * PROW;            // 135168
    const int SC_SMEM = 2 * 128 * SROW + 2048;     // 71680 (3 CTAs/SM)
    const int Y_SMEM  = 3 * 2 * 128 * FROW;        // 110592
    cudaFuncSetAttribute(proj_mma_kernel,   cudaFuncAttributeMaxDynamicSharedMemorySize, P_SMEM);
    cudaFuncSetAttribute(scores_mma_kernel, cudaFuncAttributeMaxDynamicSharedMemorySize, SC_SMEM);
    cudaFuncSetAttribute(y_out_kernel,      cudaFuncAttributeMaxDynamicSharedMemorySize, Y_SMEM);

    wconv_kernel     <<<512, 256>>>(w1, w2, w3, w4);
    xT_kernel        <<<dim3(NPIX / 32, CDIM / 32, BATCH), dim3(32, 8)>>>(x);
    proj_mma_kernel  <<<dim3(NPIX / 128, 3, BATCH), 256, P_SMEM>>>(b1, b2, b3);
    scores_mma_kernel<<<dim3(NPIX / 128, NPIX / 128, BATCH), 256, SC_SMEM>>>();
    denscale_kernel  <<<dim3(NPIX / 1024, BATCH), 256>>>();
    y_out_kernel     <<<dim3(NPIX / 128, BATCH), 256, Y_SMEM>>>(x, b4, out);
}

// round 15
// speedup vs baseline: 1.8551x; 1.2914x over previous
#include <cuda_runtime.h>
#include <cuda_fp16.h>
#include <math.h>
#include <stdint.h>

#define BATCH 4
#define CDIM  256
#define CHALF 128
#define NPIX  4096

// ---- scratch (device globals; no dynamic allocation allowed) ----
__device__ __half d_wb [3 * CHALF * CDIM];            // w1|w2|w3 f16 [3][128][256]
__device__ __half d_w4b[CDIM * CHALF];                // w4 f16 [256][128]
__device__ __half d_xT [BATCH * NPIX * CDIM];         // x^T [b][n][c] f16
__device__ __half d_thT[BATCH * NPIX * CHALF];        // theta^T [b][i][c] f16
__device__ __half d_phT[BATCH * NPIX * CHALF];        // phi^T   [b][j][c] f16
__device__ __half d_gu [BATCH * CHALF * NPIX];        // g unscaled [b][c][j] f16
__device__ __align__(128) uint8_t d_gs8[BATCH * CHALF * NPIX];  // g*4096/den e4m3 [b][c][j]
__device__ float  d_den [BATCH * NPIX];
__device__ float  d_denp[BATCH * 32 * NPIX];
__device__ __align__(128) uint8_t d_E[(size_t)BATCH * NPIX * NPIX]; // exp(scores) e4m3, 64 MB

// ================= helpers =================
__device__ __forceinline__ uint32_t smem_u32(const void* p) {
    uint32_t a;
    asm("{ .reg .u64 t; cvta.to.shared.u64 t, %1; cvt.u32.u64 %0, t; }" : "=r"(a) : "l"(p));
    return a;
}
__device__ __forceinline__ uint32_t pack_f16x2(float lo, float hi) {
    __half2 h = __floats2half2_rn(lo, hi);
    return *(uint32_t*)&h;
}
__device__ __forceinline__ uint16_t pack_e4m3x2(float lo, float hi) {
    uint16_t r;
    asm("cvt.rn.satfinite.e4m3x2.f32 %0, %1, %2;" : "=h"(r) : "f"(hi), "f"(lo));
    return r;
}
__device__ __forceinline__ void ldm_x4(uint32_t& r0, uint32_t& r1, uint32_t& r2, uint32_t& r3,
                                       uint32_t addr) {
    asm volatile("ldmatrix.sync.aligned.m8n8.x4.shared.b16 {%0,%1,%2,%3}, [%4];"
                 : "=r"(r0), "=r"(r1), "=r"(r2), "=r"(r3) : "r"(addr));
}
__device__ __forceinline__ void mma_f16(float* c, const uint32_t* a, const uint32_t* b) {
    asm volatile(
        "mma.sync.aligned.m16n8k16.row.col.f32.f16.f16.f32 "
        "{%0,%1,%2,%3}, {%4,%5,%6,%7}, {%8,%9}, {%0,%1,%2,%3};"
        : "+f"(c[0]), "+f"(c[1]), "+f"(c[2]), "+f"(c[3])
        : "r"(a[0]), "r"(a[1]), "r"(a[2]), "r"(a[3]), "r"(b[0]), "r"(b[1]));
}
__device__ __forceinline__ void mma_f16acc(uint32_t* c, const uint32_t* a, const uint32_t* b) {
    asm volatile(
        "mma.sync.aligned.m16n8k16.row.col.f16.f16.f16.f16 "
        "{%0,%1}, {%2,%3,%4,%5}, {%6,%7}, {%0,%1};"
        : "+r"(c[0]), "+r"(c[1])
        : "r"(a[0]), "r"(a[1]), "r"(a[2]), "r"(a[3]), "r"(b[0]), "r"(b[1]));
}
__device__ __forceinline__ void mma_e4m3(float* c, const uint32_t* a, const uint32_t* b) {
    asm volatile(
        "mma.sync.aligned.m16n8k32.row.col.f32.e4m3.e4m3.f32 "
        "{%0,%1,%2,%3}, {%4,%5,%6,%7}, {%8,%9}, {%0,%1,%2,%3};"
        : "+f"(c[0]), "+f"(c[1]), "+f"(c[2]), "+f"(c[3])
        : "r"(a[0]), "r"(a[1]), "r"(a[2]), "r"(a[3]), "r"(b[0]), "r"(b[1]));
}
__device__ __forceinline__ void cp16(uint32_t dst, const void* src) {
    asm volatile("cp.async.cg.shared.global [%0], [%1], 16;" :: "r"(dst), "l"(src) : "memory");
}
__device__ __forceinline__ void cp_commit() { asm volatile("cp.async.commit_group;" ::: "memory"); }
__device__ __forceinline__ void cp_wait0()  { asm volatile("cp.async.wait_group 0;" ::: "memory"); }
__device__ __forceinline__ void cp_wait1()  { asm volatile("cp.async.wait_group 1;" ::: "memory"); }

#define SROW 272   // 128 f16 row + 16B pad
#define PROW 528   // 256 f16 row + 16B pad
#define FROW 144   // 128 fp8 row + 16B pad

// ============================================================
// Kernel 0a: weight convert to f16
// ============================================================
__global__ void wconv_kernel(const float* __restrict__ w1, const float* __restrict__ w2,
                             const float* __restrict__ w3, const float* __restrict__ w4)
{
    int idx = blockIdx.x * 256 + threadIdx.x;   // 131072 total
    if (idx < 98304) {
        int sel = idx >> 15, r = idx & 32767;
        const float* W = (sel == 0) ? w1 : (sel == 1) ? w2 : w3;
        d_wb[idx] = __float2half(W[r]);
    } else {
        int r = idx - 98304;
        d_w4b[r] = __float2half(w4[r]);
    }
}

// ============================================================
// Kernel 0b: x transpose-convert: [b][c][n] fp32 -> [b][n][c] f16
// ============================================================
__global__ void xT_kernel(const float* __restrict__ x)
{
    __shared__ float t[32][33];
    const int n0 = blockIdx.x * 32, c0 = blockIdx.y * 32, b = blockIdx.z;
    const float* xb = x + ((size_t)b * CDIM + c0) * NPIX + n0;
    for (int r = threadIdx.y; r < 32; r += 8)
        t[r][threadIdx.x] = xb[(size_t)r * NPIX + threadIdx.x];
    __syncthreads();
    __half* o = d_xT + ((size_t)b * NPIX + n0) * CDIM + c0;
    for (int r = threadIdx.y; r < 32; r += 8)
        o[(size_t)r * CDIM + threadIdx.x] = __float2half(t[threadIdx.x][r]);
}

// ============================================================
// Kernel 1: proj via mma (f16 in, f32 acc). M=128, N=128, K=256.
// sel 0/1 -> thT/phT f16 [n][m]; sel 2 -> gu f16 [m][n].
// ============================================================
__global__ __launch_bounds__(256) void proj_mma_kernel(
    const float* __restrict__ b1, const float* __restrict__ b2, const float* __restrict__ b3)
{
    extern __shared__ __align__(16) char smem[];
    char* Asm = smem;               // 128*528 = 67584
    char* Bsm = smem + 67584;
    const uint32_t Asb = smem_u32(Asm), Bsb = smem_u32(Bsm);

    const int tid = threadIdx.x, wid = tid >> 5, lane = tid & 31;
    const int n0 = blockIdx.x * 128, sel = blockIdx.y, b = blockIdx.z;
    const float* Bv = (sel == 0) ? b1 : (sel == 1) ? b2 : b3;

    const __half* W = d_wb + (size_t)sel * CHALF * CDIM;
    const __half* X = d_xT + ((size_t)b * NPIX + n0) * CDIM;

#pragma unroll
    for (int e = 0; e < 16; ++e) {
        int idx = e * 256 + tid;
        int row = idx >> 5, kb = idx & 31;
        cp16(Asb + row * PROW + kb * 16, W + (size_t)row * CDIM + kb * 8);
        cp16(Bsb + row * PROW + kb * 16, X + (size_t)row * CDIM + kb * 8);
    }
    cp_commit(); cp_wait0();
    __syncthreads();

    const int wm = (wid & 3) * 32, wn = (wid >> 2) * 64;
    const int id = lane >> 3, l7 = lane & 7;

    float acc[2][8][4];
#pragma unroll
    for (int am = 0; am < 2; ++am)
#pragma unroll
        for (int an = 0; an < 8; ++an)
#pragma unroll
            for (int q = 0; q < 4; ++q) acc[am][an][q] = 0.f;

#pragma unroll
    for (int ks = 0; ks < 16; ++ks) {
        uint32_t a[2][4];
#pragma unroll
        for (int am = 0; am < 2; ++am) {
            uint32_t addr = Asb + (uint32_t)(wm + am * 16 + (id & 1) * 8 + l7) * PROW
                          + (uint32_t)(ks * 16 + (id >> 1) * 8) * 2;
            ldm_x4(a[am][0], a[am][1], a[am][2], a[am][3], addr);
        }
        uint32_t bf[8][2];
#pragma unroll
        for (int p = 0; p < 4; ++p) {
            uint32_t r0, r1, r2, r3;
            uint32_t addr = Bsb + (uint32_t)(wn + p * 16 + (id >> 1) * 8 + l7) * PROW
                          + (uint32_t)(ks * 16 + (id & 1) * 8) * 2;
            ldm_x4(r0, r1, r2, r3, addr);
            bf[p * 2][0] = r0; bf[p * 2][1] = r1;
            bf[p * 2 + 1][0] = r2; bf[p * 2 + 1][1] = r3;
        }
#pragma unroll
        for (int am = 0; am < 2; ++am)
#pragma unroll
            for (int an = 0; an < 8; ++an)
                mma_f16(acc[am][an], a[am], bf[an]);
    }
    __syncthreads();

    char* Es = smem;
    const int gID = lane >> 2, tig = lane & 3;

    if (sel < 2) {
        // stage transposed [n][m] f16 (stride 272), bias per m
#pragma unroll
        for (int am = 0; am < 2; ++am) {
            float bias0 = Bv[wm + am * 16 + gID];
            float bias1 = Bv[wm + am * 16 + gID + 8];
            int mm = wm + am * 16 + gID;
#pragma unroll
            for (int an = 0; an < 8; ++an) {
                int nn = wn + an * 8 + 2 * tig;
                *(__half*)(Es + nn * SROW + mm * 2)             = __float2half(acc[am][an][0] + bias0);
                *(__half*)(Es + (nn + 1) * SROW + mm * 2)       = __float2half(acc[am][an][1] + bias0);
                *(__half*)(Es + nn * SROW + (mm + 8) * 2)       = __float2half(acc[am][an][2] + bias1);
                *(__half*)(Es + (nn + 1) * SROW + (mm + 8) * 2) = __float2half(acc[am][an][3] + bias1);
            }
        }
        __syncthreads();
        __half* O = ((sel == 0) ? d_thT : d_phT) + (size_t)b * NPIX * CHALF;
#pragma unroll
        for (int e = 0; e < 8; ++e) {
            int idx = e * 256 + tid;
            int row = idx >> 4, kb = idx & 15;
            *(uint4*)(O + (size_t)(n0 + row) * CHALF + kb * 8) = *(const uint4*)(Es + row * SROW + kb * 16);
        }
    } else {
        // stage [m][n] f16 (stride 272), bias per m
#pragma unroll
        for (int am = 0; am < 2; ++am) {
            float bias0 = Bv[wm + am * 16 + gID];
            float bias1 = Bv[wm + am * 16 + gID + 8];
            int mm = wm + am * 16 + gID;
#pragma unroll
            for (int an = 0; an < 8; ++an) {
                int nn = wn + an * 8 + 2 * tig;
                *(uint32_t*)(Es + mm * SROW + nn * 2)       = pack_f16x2(acc[am][an][0] + bias0, acc[am][an][1] + bias0);
                *(uint32_t*)(Es + (mm + 8) * SROW + nn * 2) = pack_f16x2(acc[am][an][2] + bias1, acc[am][an][3] + bias1);
            }
        }
        __syncthreads();
        __half* O = d_gu + (size_t)b * CHALF * NPIX;
#pragma unroll
        for (int e = 0; e < 8; ++e) {
            int idx = e * 256 + tid;
            int row = idx >> 4, kb = idx & 15;
            *(uint4*)(O + (size_t)row * NPIX + n0 + kb * 8) = *(const uint4*)(Es + row * SROW + kb * 16);
        }
    }
}

// ============================================================
// Kernel 2: scores via mma (f16 in, f16 acc, 3 CTAs/SM).
// CTA tile 128(i) x 128(j), K=128. E -> e4m3 gmem; col sums (fp32) via shfl.
// ============================================================
__global__ __launch_bounds__(256, 3) void scores_mma_kernel()
{
    extern __shared__ __align__(16) char smem[];
    char* Asm = smem;              // 128 * 272 = 34816
    char* Bsm = smem + 34816;
    float* sums = (float*)(smem + 69632);   // [4][128] fp32 = 2KB
    const uint32_t Asb = smem_u32(Asm), Bsb = smem_u32(Bsm);

    const int tid = threadIdx.x, wid = tid >> 5, lane = tid & 31;
    const int j0 = blockIdx.x * 128, i0 = blockIdx.y * 128, b = blockIdx.z;

    const __half* Ath = d_thT + ((size_t)b * NPIX + i0) * CHALF;
    const __half* Bph = d_phT + ((size_t)b * NPIX + j0) * CHALF;

#pragma unroll
    for (int e = 0; e < 8; ++e) {
        int idx = e * 256 + tid;
        int row = idx >> 4, kb = idx & 15;
        cp16(Asb + row * SROW + kb * 16, Ath + (size_t)row * CHALF + kb * 8);
        cp16(Bsb + row * SROW + kb * 16, Bph + (size_t)row * CHALF + kb * 8);
    }
    cp_commit(); cp_wait0();
    __syncthreads();

    const int wm = (wid & 3) * 32, wn = (wid >> 2) * 64;
    const int id = lane >> 3, l7 = lane & 7;

    uint32_t acc[2][8][2];   // f16x2 accumulators
#pragma unroll
    for (int am = 0; am < 2; ++am)
#pragma unroll
        for (int an = 0; an < 8; ++an) { acc[am][an][0] = 0u; acc[am][an][1] = 0u; }

#pragma unroll
    for (int ks = 0; ks < 8; ++ks) {
        uint32_t a[2][4];
#pragma unroll
        for (int am = 0; am < 2; ++am) {
            uint32_t addr = Asb + (uint32_t)(wm + am * 16 + (id & 1) * 8 + l7) * SROW
                          + (uint32_t)(ks * 16 + (id >> 1) * 8) * 2;
            ldm_x4(a[am][0], a[am][1], a[am][2], a[am][3], addr);
        }
        uint32_t bf[8][2];
#pragma unroll
        for (int p = 0; p < 4; ++p) {
            uint32_t r0, r1, r2, r3;
            uint32_t addr = Bsb + (uint32_t)(wn + p * 16 + (id >> 1) * 8 + l7) * SROW
                          + (uint32_t)(ks * 16 + (id & 1) * 8) * 2;
            ldm_x4(r0, r1, r2, r3, addr);
            bf[p * 2][0] = r0; bf[p * 2][1] = r1;
            bf[p * 2 + 1][0] = r2; bf[p * 2 + 1][1] = r3;
        }
#pragma unroll
        for (int am = 0; am < 2; ++am)
#pragma unroll
            for (int an = 0; an < 8; ++an)
                mma_f16acc(acc[am][an], a[am], bf[an]);
    }
    __syncthreads();   // tile reads done; reuse smem as staging

    // epilogue: per-fragment exp -> stage e4m3 E (stride FROW) + running col sums
    char* Es = smem;
    const int gID = lane >> 2, tig = lane & 3;
    float s[8][2];
#pragma unroll
    for (int an = 0; an < 8; ++an) { s[an][0] = 0.f; s[an][1] = 0.f; }

#pragma unroll
    for (int am = 0; am < 2; ++am)
#pragma unroll
        for (int an = 0; an < 8; ++an) {
            float2 f0 = __half22float2(*(__half2*)&acc[am][an][0]);
            float2 f1 = __half22float2(*(__half2*)&acc[am][an][1]);
            float e0 = __expf(f0.x), e1 = __expf(f0.y);
            float e2 = __expf(f1.x), e3 = __expf(f1.y);
            int m0 = wm + am * 16, n0 = wn + an * 8 + 2 * tig;
            *(uint16_t*)(Es + (m0 + gID) * FROW + n0)     = pack_e4m3x2(e0, e1);
            *(uint16_t*)(Es + (m0 + gID + 8) * FROW + n0) = pack_e4m3x2(e2, e3);
            s[an][0] += e0 + e2;
            s[an][1] += e1 + e3;
        }

#pragma unroll
    for (int an = 0; an < 8; ++an) {
        float s0 = s[an][0], s1 = s[an][1];
        s0 += __shfl_xor_sync(0xffffffffu, s0, 4);
        s0 += __shfl_xor_sync(0xffffffffu, s0, 8);
        s0 += __shfl_xor_sync(0xffffffffu, s0, 16);
        s1 += __shfl_xor_sync(0xffffffffu, s1, 4);
        s1 += __shfl_xor_sync(0xffffffffu, s1, 8);
        s1 += __shfl_xor_sync(0xffffffffu, s1, 16);
        if (lane < 4) {
            int col = wn + an * 8 + 2 * lane;
            sums[(wid & 3) * 128 + col]     = s0;
            sums[(wid & 3) * 128 + col + 1] = s1;
        }
    }
    __syncthreads();

    // write E tile (coalesced) + den partials
    uint8_t* Eb = d_E + ((size_t)b * NPIX + i0) * NPIX + j0;
#pragma unroll
    for (int e = 0; e < 4; ++e) {
        int idx = e * 256 + tid;
        int row = idx >> 3, kb = idx & 7;
        *(uint4*)(Eb + (size_t)row * NPIX + kb * 16) = *(const uint4*)(Es + row * FROW + kb * 16);
    }
    if (tid < 128)
        d_denp[((size_t)b * 32 + blockIdx.y) * NPIX + j0 + tid]
            = sums[tid] + sums[128 + tid] + sums[256 + tid] + sums[384 + tid];
}

// ============================================================
// Kernel 3: den reduce over 32 i-tile partials (deterministic, float4)
// ============================================================
__global__ void den_reduce_kernel()
{
    int j = blockIdx.x * 1024 + threadIdx.x * 4;
    int b = blockIdx.y;
    float4 s = make_float4(0.f, 0.f, 0.f, 0.f);
#pragma unroll
    for (int t = 0; t < 32; ++t) {
        float4 v = *(const float4*)&d_denp[((size_t)b * 32 + t) * NPIX + j];
        s.x += v.x; s.y += v.y; s.z += v.z; s.w += v.w;
    }
    *(float4*)&d_den[b * NPIX + j] = s;
}

// ============================================================
// Kernel 4: gs8[b][c][j] = e4m3(gu[b][c][j] * 4096 / den[j])
// ============================================================
__global__ void gscale_kernel()
{
    int idx = blockIdx.x * 256 + threadIdx.x;
    int j  = (idx & (NPIX / 8 - 1)) * 8;
    int c  = (idx >> 9) & (CHALF - 1);
    int b  = idx >> 16;
    size_t off = ((size_t)b * CHALF + c) * NPIX + j;
    uint4 gv = *(const uint4*)(d_gu + off);
    const float* dp = d_den + b * NPIX + j;
    float4 e0 = *(const float4*)&dp[0], e1 = *(const float4*)&dp[4];
    const uint32_t* h = (const uint32_t*)&gv;
    float gf[8];
#pragma unroll
    for (int q = 0; q < 4; ++q) {
        float2 f = __half22float2(*(__half2*)&h[q]);
        gf[2 * q] = f.x; gf[2 * q + 1] = f.y;
    }
    uint32_t w0 = (uint32_t)pack_e4m3x2(gf[0] * 4096.f / e0.x, gf[1] * 4096.f / e0.y)
                | ((uint32_t)pack_e4m3x2(gf[2] * 4096.f / e0.z, gf[3] * 4096.f / e0.w) << 16);
    uint32_t w1 = (uint32_t)pack_e4m3x2(gf[4] * 4096.f / e1.x, gf[5] * 4096.f / e1.y)
                | ((uint32_t)pack_e4m3x2(gf[6] * 4096.f / e1.z, gf[7] * 4096.f / e1.w) << 16);
    *(uint2*)(d_gs8 + off) = make_uint2(w0, w1);
}

// ============================================================
// Kernel 5 (FUSED y + out): y via fp8 mma (3-stage pipeline), then
// out = w4*y + b4 + x in-CTA.
// smem: 3 stages x 36864 = 110592. Post-loop: y @0 (34816), w4 @36864 (+69632).
// ============================================================
__global__ __launch_bounds__(256) void y_out_kernel(
    const float* __restrict__ x, const float* __restrict__ b4, float* __restrict__ out)
{
    extern __shared__ __align__(16) char smem[];
    const uint32_t sb = smem_u32(smem);

    const int tid = threadIdx.x, wid = tid >> 5, lane = tid & 31;
    const int i0 = blockIdx.x * 128, b = blockIdx.y;

    const uint8_t* Ebase = d_E   + ((size_t)b * NPIX + i0) * NPIX;
    const uint8_t* Gbase = d_gs8 + (size_t)b * CHALF * NPIX;

    const int wm = (wid & 3) * 32, wn = (wid >> 2) * 64;
    const int id = lane >> 3, l7 = lane & 7;

    float accf[2][8][4];
#pragma unroll
    for (int am = 0; am < 2; ++am)
#pragma unroll
        for (int an = 0; an < 8; ++an)
#pragma unroll
            for (int q = 0; q < 4; ++q) accf[am][an][q] = 0.f;

    auto issue_chunk = [&](int c) {
        uint32_t st = sb + (uint32_t)(c % 3) * 36864;
        size_t k0 = (size_t)c * 128;
#pragma unroll
        for (int e = 0; e < 4; ++e) {
            int idx = e * 256 + tid;
            int row = idx >> 3, kb = idx & 7;
            cp16(st + row * FROW + kb * 16,         Ebase + (size_t)row * NPIX + k0 + kb * 16);
            cp16(st + 18432 + row * FROW + kb * 16, Gbase + (size_t)row * NPIX + k0 + kb * 16);
        }
    };

    issue_chunk(0); cp_commit();
    issue_chunk(1); cp_commit();

    for (int c = 0; c < 32; ++c) {
        if (c < 31) cp_wait1(); else cp_wait0();
        __syncthreads();
        if (c + 2 < 32) { issue_chunk(c + 2); cp_commit(); }

        uint32_t Ab = sb + (uint32_t)(c % 3) * 36864;
        uint32_t Bb = Ab + 18432;
#pragma unroll
        for (int ks = 0; ks < 4; ++ks) {            // k32 steps over 128
            uint32_t a[2][4];
#pragma unroll
            for (int am = 0; am < 2; ++am) {
                uint32_t addr = Ab + (uint32_t)(wm + am * 16 + (id & 1) * 8 + l7) * FROW
                              + (uint32_t)(ks * 32 + (id >> 1) * 16);
                ldm_x4(a[am][0], a[am][1], a[am][2], a[am][3], addr);
            }
            uint32_t bf[8][2];
#pragma unroll
            for (int p = 0; p < 4; ++p) {
                uint32_t r0, r1, r2, r3;
                uint32_t addr = Bb + (uint32_t)(wn + p * 16 + (id >> 1) * 8 + l7) * FROW
                              + (uint32_t)(ks * 32 + (id & 1) * 16);
                ldm_x4(r0, r1, r2, r3, addr);
                bf[p * 2][0] = r0; bf[p * 2][1] = r1;
                bf[p * 2 + 1][0] = r2; bf[p * 2 + 1][1] = r3;
            }
#pragma unroll
            for (int am = 0; am < 2; ++am)
#pragma unroll
                for (int an = 0; an < 8; ++an)
                    mma_e4m3(accf[am][an], a[am], bf[an]);
        }
    }
    __syncthreads();   // mainloop smem free

    // stage y = accf * (1/4096) as f16 [m=i][n=c] at smem+0;
    // concurrently cp.async w4 [256][128] f16 into smem+36864
    const float S = 1.f / 4096.f;
    char* Ys = smem;
    const uint32_t Wb = sb + 36864;
    const int gID = lane >> 2, tig = lane & 3;
#pragma unroll
    for (int e = 0; e < 16; ++e) {
        int idx = e * 256 + tid;
        int row = idx >> 4, kb = idx & 15;
        cp16(Wb + row * SROW + kb * 16, d_w4b + (size_t)row * CHALF + kb * 8);
    }
    cp_commit();
#pragma unroll
    for (int am = 0; am < 2; ++am)
#pragma unroll
        for (int an = 0; an < 8; ++an) {
            int mm = wm + am * 16 + gID, nn = wn + an * 8 + 2 * tig;
            *(uint32_t*)(Ys + mm * SROW + nn * 2)       = pack_f16x2(accf[am][an][0] * S, accf[am][an][1] * S);
            *(uint32_t*)(Ys + (mm + 8) * SROW + nn * 2) = pack_f16x2(accf[am][an][2] * S, accf[am][an][3] * S);
        }
    cp_wait0();
    __syncthreads();

    // out GEMM: two o-halves of 128. A = w4 rows (o), B = y rows (i), K = c.
    const uint32_t Yb = sb;
    for (int h = 0; h < 2; ++h) {
        int o0 = h * 128;
        float acc2[2][8][4];
#pragma unroll
        for (int am = 0; am < 2; ++am)
#pragma unroll
            for (int an = 0; an < 8; ++an)
#pragma unroll
                for (int q = 0; q < 4; ++q) acc2[am][an][q] = 0.f;

#pragma unroll
        for (int ks = 0; ks < 8; ++ks) {
            uint32_t a[2][4];
#pragma unroll
            for (int am = 0; am < 2; ++am) {
                uint32_t addr = Wb + (uint32_t)(o0 + wm + am * 16 + (id & 1) * 8 + l7) * SROW
                              + (uint32_t)(ks * 16 + (id >> 1) * 8) * 2;
                ldm_x4(a[am][0], a[am][1], a[am][2], a[am][3], addr);
            }
            uint32_t bf[8][2];
#pragma unroll
            for (int p = 0; p < 4; ++p) {
                uint32_t r0, r1, r2, r3;
                uint32_t addr = Yb + (uint32_t)(wn + p * 16 + (id >> 1) * 8 + l7) * SROW
                              + (uint32_t)(ks * 16 + (id & 1) * 8) * 2;
                ldm_x4(r0, r1, r2, r3, addr);
                bf[p * 2][0] = r0; bf[p * 2][1] = r1;
                bf[p * 2 + 1][0] = r2; bf[p * 2 + 1][1] = r3;
            }
#pragma unroll
            for (int am = 0; am < 2; ++am)
#pragma unroll
                for (int an = 0; an < 8; ++an)
                    mma_f16(acc2[am][an], a[am], bf[an]);
        }

#pragma unroll
        for (int am = 0; am < 2; ++am) {
            int mo0 = o0 + wm + am * 16 + gID;
            int mo1 = mo0 + 8;
            float bias0 = b4[mo0], bias1 = b4[mo1];
#pragma unroll
            for (int an = 0; an < 8; ++an) {
                int nn = i0 + wn + an * 8 + 2 * tig;
                size_t off0 = ((size_t)b * CDIM + mo0) * NPIX + nn;
                size_t off1 = ((size_t)b * CDIM + mo1) * NPIX + nn;
                float2 x0 = *(const float2*)&x[off0];
                float2 x1 = *(const float2*)&x[off1];
                *(float2*)&out[off0] = make_float2(acc2[am][an][0] + bias0 + x0.x,
                                                   acc2[am][an][1] + bias0 + x0.y);
                *(float2*)&out[off1] = make_float2(acc2[am][an][2] + bias1 + x1.x,
                                                   acc2[am][an][3] + bias1 + x1.y);
            }
        }
    }
}

// ============================================================
extern "C" void kernel_launch(void* const* d_in, const int* in_sizes, int n_in,
                              void* d_out, int out_size)
{
    const float* x  = (const float*)d_in[0];
    const float* w1 = (const float*)d_in[1];
    const float* b1 = (const float*)d_in[2];
    const float* w2 = (const float*)d_in[3];
    const float* b2 = (const float*)d_in[4];
    const float* w3 = (const float*)d_in[5];
    const float* b3 = (const float*)d_in[6];
    const float* w4 = (const float*)d_in[7];
    const float* b4 = (const float*)d_in[8];
    float* out = (float*)d_out;

    const int P_SMEM  = 2 * 128 * PROW;            // 135168
    const int SC_SMEM = 2 * 128 * SROW + 2048;     // 71680 (3 CTAs/SM)
    const int Y_SMEM  = 3 * 2 * 128 * FROW;        // 110592
    cudaFuncSetAttribute(proj_mma_kernel,   cudaFuncAttributeMaxDynamicSharedMemorySize, P_SMEM);
    cudaFuncSetAttribute(scores_mma_kernel, cudaFuncAttributeMaxDynamicSharedMemorySize, SC_SMEM);
    cudaFuncSetAttribute(y_out_kernel,      cudaFuncAttributeMaxDynamicSharedMemorySize, Y_SMEM);

    wconv_kernel     <<<512, 256>>>(w1, w2, w3, w4);
    xT_kernel        <<<dim3(NPIX / 32, CDIM / 32, BATCH), dim3(32, 8)>>>(x);
    proj_mma_kernel  <<<dim3(NPIX / 128, 3, BATCH), 256, P_SMEM>>>(b1, b2, b3);
    scores_mma_kernel<<<dim3(NPIX / 128, NPIX / 128, BATCH), 256, SC_SMEM>>>();
    den_reduce_kernel<<<dim3(NPIX / 1024, BATCH), 256>>>();
    gscale_kernel    <<<dim3(1024), 256>>>();
    y_out_kernel     <<<dim3(NPIX / 128, BATCH), 256, Y_SMEM>>>(x, b4, out);
}

// round 16
// speedup vs baseline: 1.8565x; 1.0008x over previous
#include <cuda_runtime.h>
#include <cuda_fp16.h>
#include <math.h>
#include <stdint.h>

#define BATCH 4
#define CDIM  256
#define CHALF 128
#define NPIX  4096

// ---- scratch (device globals; no dynamic allocation allowed) ----
__device__ __half d_wb [3 * CHALF * CDIM];            // w1|w2|w3 f16 [3][128][256]
__device__ __half d_w4b[CDIM * CHALF];                // w4 f16 [256][128]
__device__ __half d_xT [BATCH * NPIX * CDIM];         // x^T [b][n][c] f16
__device__ __half d_thT[BATCH * NPIX * CHALF];        // theta^T [b][i][c] f16
__device__ __half d_phT[BATCH * NPIX * CHALF];        // phi^T   [b][j][c] f16
__device__ __half d_gu [BATCH * CHALF * NPIX];        // g unscaled [b][c][j] f16
__device__ __align__(128) uint8_t d_gs8[BATCH * CHALF * NPIX];  // g*4096/den e4m3 [b][c][j]
__device__ float  d_den [BATCH * NPIX];
__device__ float  d_denp[BATCH * 32 * NPIX];
__device__ __align__(128) uint8_t d_E[(size_t)BATCH * NPIX * NPIX]; // exp(scores) e4m3, 64 MB

// ================= helpers =================
__device__ __forceinline__ uint32_t smem_u32(const void* p) {
    uint32_t a;
    asm("{ .reg .u64 t; cvta.to.shared.u64 t, %1; cvt.u32.u64 %0, t; }" : "=r"(a) : "l"(p));
    return a;
}
__device__ __forceinline__ uint32_t pack_f16x2(float lo, float hi) {
    __half2 h = __floats2half2_rn(lo, hi);
    return *(uint32_t*)&h;
}
__device__ __forceinline__ uint16_t pack_e4m3x2(float lo, float hi) {
    uint16_t r;
    asm("cvt.rn.satfinite.e4m3x2.f32 %0, %1, %2;" : "=h"(r) : "f"(hi), "f"(lo));
    return r;
}
__device__ __forceinline__ void ldm_x4(uint32_t& r0, uint32_t& r1, uint32_t& r2, uint32_t& r3,
                                       uint32_t addr) {
    asm volatile("ldmatrix.sync.aligned.m8n8.x4.shared.b16 {%0,%1,%2,%3}, [%4];"
                 : "=r"(r0), "=r"(r1), "=r"(r2), "=r"(r3) : "r"(addr));
}
__device__ __forceinline__ void mma_f16(float* c, const uint32_t* a, const uint32_t* b) {
    asm volatile(
        "mma.sync.aligned.m16n8k16.row.col.f32.f16.f16.f32 "
        "{%0,%1,%2,%3}, {%4,%5,%6,%7}, {%8,%9}, {%0,%1,%2,%3};"
        : "+f"(c[0]), "+f"(c[1]), "+f"(c[2]), "+f"(c[3])
        : "r"(a[0]), "r"(a[1]), "r"(a[2]), "r"(a[3]), "r"(b[0]), "r"(b[1]));
}
__device__ __forceinline__ void mma_f16acc(uint32_t* c, const uint32_t* a, const uint32_t* b) {
    asm volatile(
        "mma.sync.aligned.m16n8k16.row.col.f16.f16.f16.f16 "
        "{%0,%1}, {%2,%3,%4,%5}, {%6,%7}, {%0,%1};"
        : "+r"(c[0]), "+r"(c[1])
        : "r"(a[0]), "r"(a[1]), "r"(a[2]), "r"(a[3]), "r"(b[0]), "r"(b[1]));
}
__device__ __forceinline__ void mma_e4m3(float* c, const uint32_t* a, const uint32_t* b) {
    asm volatile(
        "mma.sync.aligned.m16n8k32.row.col.f32.e4m3.e4m3.f32 "
        "{%0,%1,%2,%3}, {%4,%5,%6,%7}, {%8,%9}, {%0,%1,%2,%3};"
        : "+f"(c[0]), "+f"(c[1]), "+f"(c[2]), "+f"(c[3])
        : "r"(a[0]), "r"(a[1]), "r"(a[2]), "r"(a[3]), "r"(b[0]), "r"(b[1]));
}
__device__ __forceinline__ void cp16(uint32_t dst, const void* src) {
    asm volatile("cp.async.cg.shared.global [%0], [%1], 16;" :: "r"(dst), "l"(src) : "memory");
}
__device__ __forceinline__ void cp_commit() { asm volatile("cp.async.commit_group;" ::: "memory"); }
__device__ __forceinline__ void cp_wait0()  { asm volatile("cp.async.wait_group 0;" ::: "memory"); }
__device__ __forceinline__ void cp_wait1()  { asm volatile("cp.async.wait_group 1;" ::: "memory"); }

#define SROW 272   // 128 f16 row + 16B pad
#define FROW 144   // 128 fp8 row + 16B pad

// ============================================================
// Kernel 0a: weight convert to f16
// ============================================================
__global__ void wconv_kernel(const float* __restrict__ w1, const float* __restrict__ w2,
                             const float* __restrict__ w3, const float* __restrict__ w4)
{
    int idx = blockIdx.x * 256 + threadIdx.x;   // 131072 total
    if (idx < 98304) {
        int sel = idx >> 15, r = idx & 32767;
        const float* W = (sel == 0) ? w1 : (sel == 1) ? w2 : w3;
        d_wb[idx] = __float2half(W[r]);
    } else {
        int r = idx - 98304;
        d_w4b[r] = __float2half(w4[r]);
    }
}

// ============================================================
// Kernel 0b: x transpose-convert: [b][c][n] fp32 -> [b][n][c] f16
// ============================================================
__global__ void xT_kernel(const float* __restrict__ x)
{
    __shared__ float t[32][33];
    const int n0 = blockIdx.x * 32, c0 = blockIdx.y * 32, b = blockIdx.z;
    const float* xb = x + ((size_t)b * CDIM + c0) * NPIX + n0;
    for (int r = threadIdx.y; r < 32; r += 8)
        t[r][threadIdx.x] = xb[(size_t)r * NPIX + threadIdx.x];
    __syncthreads();
    __half* o = d_xT + ((size_t)b * NPIX + n0) * CDIM + c0;
    for (int r = threadIdx.y; r < 32; r += 8)
        o[(size_t)r * CDIM + threadIdx.x] = __float2half(t[threadIdx.x][r]);
}

// ============================================================
// Kernel 1: proj via mma (f16 in, f16 acc, 3 CTAs/SM). M=128, N=128, K=256
// processed as two sequential K=128 chunks through one 68KB smem footprint.
// sel 0/1 -> thT/phT f16 [n][m]; sel 2 -> gu f16 [m][n].
// ============================================================
__global__ __launch_bounds__(256, 3) void proj_mma_kernel(
    const float* __restrict__ b1, const float* __restrict__ b2, const float* __restrict__ b3)
{
    extern __shared__ __align__(16) char smem[];
    char* Asm = smem;               // 128*272 = 34816
    char* Bsm = smem + 34816;
    const uint32_t Asb = smem_u32(Asm), Bsb = smem_u32(Bsm);

    const int tid = threadIdx.x, wid = tid >> 5, lane = tid & 31;
    const int n0 = blockIdx.x * 128, sel = blockIdx.y, b = blockIdx.z;
    const float* Bv = (sel == 0) ? b1 : (sel == 1) ? b2 : b3;

    const __half* W = d_wb + (size_t)sel * CHALF * CDIM;
    const __half* X = d_xT + ((size_t)b * NPIX + n0) * CDIM;

    const int wm = (wid & 3) * 32, wn = (wid >> 2) * 64;
    const int id = lane >> 3, l7 = lane & 7;

    uint32_t acc[2][8][2];   // f16x2 accumulators
#pragma unroll
    for (int am = 0; am < 2; ++am)
#pragma unroll
        for (int an = 0; an < 8; ++an) { acc[am][an][0] = 0u; acc[am][an][1] = 0u; }

#pragma unroll
    for (int kc = 0; kc < 2; ++kc) {
        if (kc) __syncthreads();    // prior chunk's ldmatrix reads complete
#pragma unroll
        for (int e = 0; e < 8; ++e) {
            int idx = e * 256 + tid;
            int row = idx >> 4, kb = idx & 15;
            cp16(Asb + row * SROW + kb * 16, W + (size_t)row * CDIM + kc * 128 + kb * 8);
            cp16(Bsb + row * SROW + kb * 16, X + (size_t)row * CDIM + kc * 128 + kb * 8);
        }
        cp_commit(); cp_wait0();
        __syncthreads();

#pragma unroll
        for (int ks = 0; ks < 8; ++ks) {
            uint32_t a[2][4];
#pragma unroll
            for (int am = 0; am < 2; ++am) {
                uint32_t addr = Asb + (uint32_t)(wm + am * 16 + (id & 1) * 8 + l7) * SROW
                              + (uint32_t)(ks * 16 + (id >> 1) * 8) * 2;
                ldm_x4(a[am][0], a[am][1], a[am][2], a[am][3], addr);
            }
            uint32_t bf[8][2];
#pragma unroll
            for (int p = 0; p < 4; ++p) {
                uint32_t r0, r1, r2, r3;
                uint32_t addr = Bsb + (uint32_t)(wn + p * 16 + (id >> 1) * 8 + l7) * SROW
                              + (uint32_t)(ks * 16 + (id & 1) * 8) * 2;
                ldm_x4(r0, r1, r2, r3, addr);
                bf[p * 2][0] = r0; bf[p * 2][1] = r1;
                bf[p * 2 + 1][0] = r2; bf[p * 2 + 1][1] = r3;
            }
#pragma unroll
            for (int am = 0; am < 2; ++am)
#pragma unroll
                for (int an = 0; an < 8; ++an)
                    mma_f16acc(acc[am][an], a[am], bf[an]);
        }
    }
    __syncthreads();

    char* Es = smem;
    const int gID = lane >> 2, tig = lane & 3;

    if (sel < 2) {
        // stage transposed [n][m] f16 (stride 272), bias per m
#pragma unroll
        for (int am = 0; am < 2; ++am) {
            float bias0 = Bv[wm + am * 16 + gID];
            float bias1 = Bv[wm + am * 16 + gID + 8];
            int mm = wm + am * 16 + gID;
#pragma unroll
            for (int an = 0; an < 8; ++an) {
                int nn = wn + an * 8 + 2 * tig;
                float2 f0 = __half22float2(*(__half2*)&acc[am][an][0]);
                float2 f1 = __half22float2(*(__half2*)&acc[am][an][1]);
                *(__half*)(Es + nn * SROW + mm * 2)             = __float2half(f0.x + bias0);
                *(__half*)(Es + (nn + 1) * SROW + mm * 2)       = __float2half(f0.y + bias0);
                *(__half*)(Es + nn * SROW + (mm + 8) * 2)       = __float2half(f1.x + bias1);
                *(__half*)(Es + (nn + 1) * SROW + (mm + 8) * 2) = __float2half(f1.y + bias1);
            }
        }
        __syncthreads();
        __half* O = ((sel == 0) ? d_thT : d_phT) + (size_t)b * NPIX * CHALF;
#pragma unroll
        for (int e = 0; e < 8; ++e) {
            int idx = e * 256 + tid;
            int row = idx >> 4, kb = idx & 15;
            *(uint4*)(O + (size_t)(n0 + row) * CHALF + kb * 8) = *(const uint4*)(Es + row * SROW + kb * 16);
        }
    } else {
        // stage [m][n] f16 (stride 272), bias per m
#pragma unroll
        for (int am = 0; am < 2; ++am) {
            float bias0 = Bv[wm + am * 16 + gID];
            float bias1 = Bv[wm + am * 16 + gID + 8];
            int mm = wm + am * 16 + gID;
#pragma unroll
            for (int an = 0; an < 8; ++an) {
                int nn = wn + an * 8 + 2 * tig;
                float2 f0 = __half22float2(*(__half2*)&acc[am][an][0]);
                float2 f1 = __half22float2(*(__half2*)&acc[am][an][1]);
                *(uint32_t*)(Es + mm * SROW + nn * 2)       = pack_f16x2(f0.x + bias0, f0.y + bias0);
                *(uint32_t*)(Es + (mm + 8) * SROW + nn * 2) = pack_f16x2(f1.x + bias1, f1.y + bias1);
            }
        }
        __syncthreads();
        __half* O = d_gu + (size_t)b * CHALF * NPIX;
#pragma unroll
        for (int e = 0; e < 8; ++e) {
            int idx = e * 256 + tid;
            int row = idx >> 4, kb = idx & 15;
            *(uint4*)(O + (size_t)row * NPIX + n0 + kb * 8) = *(const uint4*)(Es + row * SROW + kb * 16);
        }
    }
}

// ============================================================
// Kernel 2: scores via mma (f16 in, f16 acc, 3 CTAs/SM).
// CTA tile 128(i) x 128(j), K=128. E -> e4m3 gmem; col sums (fp32) via shfl.
// ============================================================
__global__ __launch_bounds__(256, 3) void scores_mma_kernel()
{
    extern __shared__ __align__(16) char smem[];
    char* Asm = smem;              // 128 * 272 = 34816
    char* Bsm = smem + 34816;
    float* sums = (float*)(smem + 69632);   // [4][128] fp32 = 2KB
    const uint32_t Asb = smem_u32(Asm), Bsb = smem_u32(Bsm);

    const int tid = threadIdx.x, wid = tid >> 5, lane = tid & 31;
    const int j0 = blockIdx.x * 128, i0 = blockIdx.y * 128, b = blockIdx.z;

    const __half* Ath = d_thT + ((size_t)b * NPIX + i0) * CHALF;
    const __half* Bph = d_phT + ((size_t)b * NPIX + j0) * CHALF;

#pragma unroll
    for (int e = 0; e < 8; ++e) {
        int idx = e * 256 + tid;
        int row = idx >> 4, kb = idx & 15;
        cp16(Asb + row * SROW + kb * 16, Ath + (size_t)row * CHALF + kb * 8);
        cp16(Bsb + row * SROW + kb * 16, Bph + (size_t)row * CHALF + kb * 8);
    }
    cp_commit(); cp_wait0();
    __syncthreads();

    const int wm = (wid & 3) * 32, wn = (wid >> 2) * 64;
    const int id = lane >> 3, l7 = lane & 7;

    uint32_t acc[2][8][2];   // f16x2 accumulators
#pragma unroll
    for (int am = 0; am < 2; ++am)
#pragma unroll
        for (int an = 0; an < 8; ++an) { acc[am][an][0] = 0u; acc[am][an][1] = 0u; }

#pragma unroll
    for (int ks = 0; ks < 8; ++ks) {
        uint32_t a[2][4];
#pragma unroll
        for (int am = 0; am < 2; ++am) {
            uint32_t addr = Asb + (uint32_t)(wm + am * 16 + (id & 1) * 8 + l7) * SROW
                          + (uint32_t)(ks * 16 + (id >> 1) * 8) * 2;
            ldm_x4(a[am][0], a[am][1], a[am][2], a[am][3], addr);
        }
        uint32_t bf[8][2];
#pragma unroll
        for (int p = 0; p < 4; ++p) {
            uint32_t r0, r1, r2, r3;
            uint32_t addr = Bsb + (uint32_t)(wn + p * 16 + (id >> 1) * 8 + l7) * SROW
                          + (uint32_t)(ks * 16 + (id & 1) * 8) * 2;
            ldm_x4(r0, r1, r2, r3, addr);
            bf[p * 2][0] = r0; bf[p * 2][1] = r1;
            bf[p * 2 + 1][0] = r2; bf[p * 2 + 1][1] = r3;
        }
#pragma unroll
        for (int am = 0; am < 2; ++am)
#pragma unroll
            for (int an = 0; an < 8; ++an)
                mma_f16acc(acc[am][an], a[am], bf[an]);
    }
    __syncthreads();   // tile reads done; reuse smem as staging

    // epilogue: per-fragment exp -> stage e4m3 E (stride FROW) + running col sums
    char* Es = smem;
    const int gID = lane >> 2, tig = lane & 3;
    float s[8][2];
#pragma unroll
    for (int an = 0; an < 8; ++an) { s[an][0] = 0.f; s[an][1] = 0.f; }

#pragma unroll
    for (int am = 0; am < 2; ++am)
#pragma unroll
        for (int an = 0; an < 8; ++an) {
            float2 f0 = __half22float2(*(__half2*)&acc[am][an][0]);
            float2 f1 = __half22float2(*(__half2*)&acc[am][an][1]);
            float e0 = __expf(f0.x), e1 = __expf(f0.y);
            float e2 = __expf(f1.x), e3 = __expf(f1.y);
            int m0 = wm + am * 16, n0 = wn + an * 8 + 2 * tig;
            *(uint16_t*)(Es + (m0 + gID) * FROW + n0)     = pack_e4m3x2(e0, e1);
            *(uint16_t*)(Es + (m0 + gID + 8) * FROW + n0) = pack_e4m3x2(e2, e3);
            s[an][0] += e0 + e2;
            s[an][1] += e1 + e3;
        }

#pragma unroll
    for (int an = 0; an < 8; ++an) {
        float s0 = s[an][0], s1 = s[an][1];
        s0 += __shfl_xor_sync(0xffffffffu, s0, 4);
        s0 += __shfl_xor_sync(0xffffffffu, s0, 8);
        s0 += __shfl_xor_sync(0xffffffffu, s0, 16);
        s1 += __shfl_xor_sync(0xffffffffu, s1, 4);
        s1 += __shfl_xor_sync(0xffffffffu, s1, 8);
        s1 += __shfl_xor_sync(0xffffffffu, s1, 16);
        if (lane < 4) {
            int col = wn + an * 8 + 2 * lane;
            sums[(wid & 3) * 128 + col]     = s0;
            sums[(wid & 3) * 128 + col + 1] = s1;
        }
    }
    __syncthreads();

    // write E tile (coalesced) + den partials
    uint8_t* Eb = d_E + ((size_t)b * NPIX + i0) * NPIX + j0;
#pragma unroll
    for (int e = 0; e < 4; ++e) {
        int idx = e * 256 + tid;
        int row = idx >> 3, kb = idx & 7;
        *(uint4*)(Eb + (size_t)row * NPIX + kb * 16) = *(const uint4*)(Es + row * FROW + kb * 16);
    }
    if (tid < 128)
        d_denp[((size_t)b * 32 + blockIdx.y) * NPIX + j0 + tid]
            = sums[tid] + sums[128 + tid] + sums[256 + tid] + sums[384 + tid];
}

// ============================================================
// Kernel 3: den reduce over 32 i-tile partials (deterministic, float4)
// ============================================================
__global__ void den_reduce_kernel()
{
    int j = blockIdx.x * 1024 + threadIdx.x * 4;
    int b = blockIdx.y;
    float4 s = make_float4(0.f, 0.f, 0.f, 0.f);
#pragma unroll
    for (int t = 0; t < 32; ++t) {
        float4 v = *(const float4*)&d_denp[((size_t)b * 32 + t) * NPIX + j];
        s.x += v.x; s.y += v.y; s.z += v.z; s.w += v.w;
    }
    *(float4*)&d_den[b * NPIX + j] = s;
}

// ============================================================
// Kernel 4: gs8[b][c][j] = e4m3(gu[b][c][j] * 4096 / den[j])
// ============================================================
__global__ void gscale_kernel()
{
    int idx = blockIdx.x * 256 + threadIdx.x;
    int j  = (idx & (NPIX / 8 - 1)) * 8;
    int c  = (idx >> 9) & (CHALF - 1);
    int b  = idx >> 16;
    size_t off = ((size_t)b * CHALF + c) * NPIX + j;
    uint4 gv = *(const uint4*)(d_gu + off);
    const float* dp = d_den + b * NPIX + j;
    float4 e0 = *(const float4*)&dp[0], e1 = *(const float4*)&dp[4];
    const uint32_t* h = (const uint32_t*)&gv;
    float gf[8];
#pragma unroll
    for (int q = 0; q < 4; ++q) {
        float2 f = __half22float2(*(__half2*)&h[q]);
        gf[2 * q] = f.x; gf[2 * q + 1] = f.y;
    }
    uint32_t w0 = (uint32_t)pack_e4m3x2(gf[0] * 4096.f / e0.x, gf[1] * 4096.f / e0.y)
                | ((uint32_t)pack_e4m3x2(gf[2] * 4096.f / e0.z, gf[3] * 4096.f / e0.w) << 16);
    uint32_t w1 = (uint32_t)pack_e4m3x2(gf[4] * 4096.f / e1.x, gf[5] * 4096.f / e1.y)
                | ((uint32_t)pack_e4m3x2(gf[6] * 4096.f / e1.z, gf[7] * 4096.f / e1.w) << 16);
    *(uint2*)(d_gs8 + off) = make_uint2(w0, w1);
}

// ============================================================
// Kernel 5 (FUSED y + out): y via fp8 mma (3-stage pipeline), then
// out = w4*y + b4 + x in-CTA.
// smem: 3 stages x 36864 = 110592. Post-loop: y @0 (34816), w4 @36864 (+69632).
// ============================================================
__global__ __launch_bounds__(256) void y_out_kernel(
    const float* __restrict__ x, const float* __restrict__ b4, float* __restrict__ out)
{
    extern __shared__ __align__(16) char smem[];
    const uint32_t sb = smem_u32(smem);

    const int tid = threadIdx.x, wid = tid >> 5, lane = tid & 31;
    const int i0 = blockIdx.x * 128, b = blockIdx.y;

    const uint8_t* Ebase = d_E   + ((size_t)b * NPIX + i0) * NPIX;
    const uint8_t* Gbase = d_gs8 + (size_t)b * CHALF * NPIX;

    const int wm = (wid & 3) * 32, wn = (wid >> 2) * 64;
    const int id = lane >> 3, l7 = lane & 7;

    float accf[2][8][4];
#pragma unroll
    for (int am = 0; am < 2; ++am)
#pragma unroll
        for (int an = 0; an < 8; ++an)
#pragma unroll
            for (int q = 0; q < 4; ++q) accf[am][an][q] = 0.f;

    auto issue_chunk = [&](int c) {
        uint32_t st = sb + (uint32_t)(c % 3) * 36864;
        size_t k0 = (size_t)c * 128;
#pragma unroll
        for (int e = 0; e < 4; ++e) {
            int idx = e * 256 + tid;
            int row = idx >> 3, kb = idx & 7;
            cp16(st + row * FROW + kb * 16,         Ebase + (size_t)row * NPIX + k0 + kb * 16);
            cp16(st + 18432 + row * FROW + kb * 16, Gbase + (size_t)row * NPIX + k0 + kb * 16);
        }
    };

    issue_chunk(0); cp_commit();
    issue_chunk(1); cp_commit();

    for (int c = 0; c < 32; ++c) {
        if (c < 31) cp_wait1(); else cp_wait0();
        __syncthreads();
        if (c + 2 < 32) { issue_chunk(c + 2); cp_commit(); }

        uint32_t Ab = sb + (uint32_t)(c % 3) * 36864;
        uint32_t Bb = Ab + 18432;
#pragma unroll
        for (int ks = 0; ks < 4; ++ks) {            // k32 steps over 128
            uint32_t a[2][4];
#pragma unroll
            for (int am = 0; am < 2; ++am) {
                uint32_t addr = Ab + (uint32_t)(wm + am * 16 + (id & 1) * 8 + l7) * FROW
                              + (uint32_t)(ks * 32 + (id >> 1) * 16);
                ldm_x4(a[am][0], a[am][1], a[am][2], a[am][3], addr);
            }
            uint32_t bf[8][2];
#pragma unroll
            for (int p = 0; p < 4; ++p) {
                uint32_t r0, r1, r2, r3;
                uint32_t addr = Bb + (uint32_t)(wn + p * 16 + (id >> 1) * 8 + l7) * FROW
                              + (uint32_t)(ks * 32 + (id & 1) * 16);
                ldm_x4(r0, r1, r2, r3, addr);
                bf[p * 2][0] = r0; bf[p * 2][1] = r1;
                bf[p * 2 + 1][0] = r2; bf[p * 2 + 1][1] = r3;
            }
#pragma unroll
            for (int am = 0; am < 2; ++am)
#pragma unroll
                for (int an = 0; an < 8; ++an)
                    mma_e4m3(accf[am][an], a[am], bf[an]);
        }
    }
    __syncthreads();   // mainloop smem free

    // stage y = accf * (1/4096) as f16 [m=i][n=c] at smem+0;
    // concurrently cp.async w4 [256][128] f16 into smem+36864
    const float S = 1.f / 4096.f;
    char* Ys = smem;
    const uint32_t Wb = sb + 36864;
    const int gID = lane >> 2, tig = lane & 3;
#pragma unroll
    for (int e = 0; e < 16; ++e) {
        int idx = e * 256 + tid;
        int row = idx >> 4, kb = idx & 15;
        cp16(Wb + row * SROW + kb * 16, d_w4b + (size_t)row * CHALF + kb * 8);
    }
    cp_commit();
#pragma unroll
    for (int am = 0; am < 2; ++am)
#pragma unroll
        for (int an = 0; an < 8; ++an) {
            int mm = wm + am * 16 + gID, nn = wn + an * 8 + 2 * tig;
            *(uint32_t*)(Ys + mm * SROW + nn * 2)       = pack_f16x2(accf[am][an][0] * S, accf[am][an][1] * S);
            *(uint32_t*)(Ys + (mm + 8) * SROW + nn * 2) = pack_f16x2(accf[am][an][2] * S, accf[am][an][3] * S);
        }
    cp_wait0();
    __syncthreads();

    // out GEMM: two o-halves of 128. A = w4 rows (o), B = y rows (i), K = c.
    const uint32_t Yb = sb;
    for (int h = 0; h < 2; ++h) {
        int o0 = h * 128;
        float acc2[2][8][4];
#pragma unroll
        for (int am = 0; am < 2; ++am)
#pragma unroll
            for (int an = 0; an < 8; ++an)
#pragma unroll
                for (int q = 0; q < 4; ++q) acc2[am][an][q] = 0.f;

#pragma unroll
        for (int ks = 0; ks < 8; ++ks) {
            uint32_t a[2][4];
#pragma unroll
            for (int am = 0; am < 2; ++am) {
                uint32_t addr = Wb + (uint32_t)(o0 + wm + am * 16 + (id & 1) * 8 + l7) * SROW
                              + (uint32_t)(ks * 16 + (id >> 1) * 8) * 2;
                ldm_x4(a[am][0], a[am][1], a[am][2], a[am][3], addr);
            }
            uint32_t bf[8][2];
#pragma unroll
            for (int p = 0; p < 4; ++p) {
                uint32_t r0, r1, r2, r3;
                uint32_t addr = Yb + (uint32_t)(wn + p * 16 + (id >> 1) * 8 + l7) * SROW
                              + (uint32_t)(ks * 16 + (id & 1) * 8) * 2;
                ldm_x4(r0, r1, r2, r3, addr);
                bf[p * 2][0] = r0; bf[p * 2][1] = r1;
                bf[p * 2 + 1][0] = r2; bf[p * 2 + 1][1] = r3;
            }
#pragma unroll
            for (int am = 0; am < 2; ++am)
#pragma unroll
                for (int an = 0; an < 8; ++an)
                    mma_f16(acc2[am][an], a[am], bf[an]);
        }

#pragma unroll
        for (int am = 0; am < 2; ++am) {
            int mo0 = o0 + wm + am * 16 + gID;
            int mo1 = mo0 + 8;
            float bias0 = b4[mo0], bias1 = b4[mo1];
#pragma unroll
            for (int an = 0; an < 8; ++an) {
                int nn = i0 + wn + an * 8 + 2 * tig;
                size_t off0 = ((size_t)b * CDIM + mo0) * NPIX + nn;
                size_t off1 = ((size_t)b * CDIM + mo1) * NPIX + nn;
                float2 x0 = *(const float2*)&x[off0];
                float2 x1 = *(const float2*)&x[off1];
                *(float2*)&out[off0] = make_float2(acc2[am][an][0] + bias0 + x0.x,
                                                   acc2[am][an][1] + bias0 + x0.y);
                *(float2*)&out[off1] = make_float2(acc2[am][an][2] + bias1 + x1.x,
                                                   acc2[am][an][3] + bias1 + x1.y);
            }
        }
    }
}

// ============================================================
extern "C" void kernel_launch(void* const* d_in, const int* in_sizes, int n_in,
                              void* d_out, int out_size)
{
    const float* x  = (const float*)d_in[0];
    const float* w1 = (const float*)d_in[1];
    const float* b1 = (const float*)d_in[2];
    const float* w2 = (const float*)d_in[3];
    const float* b2 = (const float*)d_in[4];
    const float* w3 = (const float*)d_in[5];
    const float* b3 = (const float*)d_in[6];
    const float* w4 = (const float*)d_in[7];
    const float* b4 = (const float*)d_in[8];
    float* out = (float*)d_out;

    const int P_SMEM  = 2 * 128 * SROW;            // 69632 (3 CTAs/SM)
    const int SC_SMEM = 2 * 128 * SROW + 2048;     // 71680 (3 CTAs/SM)
    const int Y_SMEM  = 3 * 2 * 128 * FROW;        // 110592
    cudaFuncSetAttribute(proj_mma_kernel,   cudaFuncAttributeMaxDynamicSharedMemorySize, P_SMEM);
    cudaFuncSetAttribute(scores_mma_kernel, cudaFuncAttributeMaxDynamicSharedMemorySize, SC_SMEM);
    cudaFuncSetAttribute(y_out_kernel,      cudaFuncAttributeMaxDynamicSharedMemorySize, Y_SMEM);

    wconv_kernel     <<<512, 256>>>(w1, w2, w3, w4);
    xT_kernel        <<<dim3(NPIX / 32, CDIM / 32, BATCH), dim3(32, 8)>>>(x);
    proj_mma_kernel  <<<dim3(NPIX / 128, 3, BATCH), 256, P_SMEM>>>(b1, b2, b3);
    scores_mma_kernel<<<dim3(NPIX / 128, NPIX / 128, BATCH), 256, SC_SMEM>>>();
    den_reduce_kernel<<<dim3(NPIX / 1024, BATCH), 256>>>();
    gscale_kernel    <<<dim3(1024), 256>>>();
    y_out_kernel     <<<dim3(NPIX / 128, BATCH), 256, Y_SMEM>>>(x, b4, out);
}

// round 17
// speedup vs baseline: 1.9172x; 1.0327x over previous
#include <cuda_runtime.h>
#include <cuda_fp16.h>
#include <math.h>
#include <stdint.h>

#define BATCH 4
#define CDIM  256
#define CHALF 128
#define NPIX  4096

// ---- scratch (device globals; no dynamic allocation allowed) ----
__device__ __half d_wb [3 * CHALF * CDIM];            // w1|w2|w3 f16 [3][128][256]
__device__ __half d_w4b[CDIM * CHALF];                // w4 f16 [256][128]
__device__ __half d_xT [BATCH * NPIX * CDIM];         // x^T [b][n][c] f16
__device__ __align__(128) uint8_t d_thT8[BATCH * NPIX * CHALF]; // theta^T e4m3 [b][i][c]
__device__ __align__(128) uint8_t d_phT8[BATCH * NPIX * CHALF]; // phi^T   e4m3 [b][j][c]
__device__ __half d_gu [BATCH * CHALF * NPIX];        // g unscaled [b][c][j] f16
__device__ __align__(128) uint8_t d_gs8[BATCH * CHALF * NPIX];  // g*4096/den e4m3 [b][c][j]
__device__ float  d_den [BATCH * NPIX];
__device__ float  d_denp[BATCH * 32 * NPIX];
__device__ __align__(128) uint8_t d_E[(size_t)BATCH * NPIX * NPIX]; // exp(scores) e4m3, 64 MB

// ================= helpers =================
__device__ __forceinline__ uint32_t smem_u32(const void* p) {
    uint32_t a;
    asm("{ .reg .u64 t; cvta.to.shared.u64 t, %1; cvt.u32.u64 %0, t; }" : "=r"(a) : "l"(p));
    return a;
}
__device__ __forceinline__ uint32_t pack_f16x2(float lo, float hi) {
    __half2 h = __floats2half2_rn(lo, hi);
    return *(uint32_t*)&h;
}
__device__ __forceinline__ uint16_t pack_e4m3x2(float lo, float hi) {
    uint16_t r;
    asm("cvt.rn.satfinite.e4m3x2.f32 %0, %1, %2;" : "=h"(r) : "f"(hi), "f"(lo));
    return r;
}
__device__ __forceinline__ void ldm_x4(uint32_t& r0, uint32_t& r1, uint32_t& r2, uint32_t& r3,
                                       uint32_t addr) {
    asm volatile("ldmatrix.sync.aligned.m8n8.x4.shared.b16 {%0,%1,%2,%3}, [%4];"
                 : "=r"(r0), "=r"(r1), "=r"(r2), "=r"(r3) : "r"(addr));
}
__device__ __forceinline__ void mma_f16(float* c, const uint32_t* a, const uint32_t* b) {
    asm volatile(
        "mma.sync.aligned.m16n8k16.row.col.f32.f16.f16.f32 "
        "{%0,%1,%2,%3}, {%4,%5,%6,%7}, {%8,%9}, {%0,%1,%2,%3};"
        : "+f"(c[0]), "+f"(c[1]), "+f"(c[2]), "+f"(c[3])
        : "r"(a[0]), "r"(a[1]), "r"(a[2]), "r"(a[3]), "r"(b[0]), "r"(b[1]));
}
__device__ __forceinline__ void mma_f16acc(uint32_t* c, const uint32_t* a, const uint32_t* b) {
    asm volatile(
        "mma.sync.aligned.m16n8k16.row.col.f16.f16.f16.f16 "
        "{%0,%1}, {%2,%3,%4,%5}, {%6,%7}, {%0,%1};"
        : "+r"(c[0]), "+r"(c[1])
        : "r"(a[0]), "r"(a[1]), "r"(a[2]), "r"(a[3]), "r"(b[0]), "r"(b[1]));
}
__device__ __forceinline__ void mma_e4m3(float* c, const uint32_t* a, const uint32_t* b) {
    asm volatile(
        "mma.sync.aligned.m16n8k32.row.col.f32.e4m3.e4m3.f32 "
        "{%0,%1,%2,%3}, {%4,%5,%6,%7}, {%8,%9}, {%0,%1,%2,%3};"
        : "+f"(c[0]), "+f"(c[1]), "+f"(c[2]), "+f"(c[3])
        : "r"(a[0]), "r"(a[1]), "r"(a[2]), "r"(a[3]), "r"(b[0]), "r"(b[1]));
}
// fp8 inputs, f16 accumulators (2 packed regs) — keeps register pressure low
__device__ __forceinline__ void mma_e4m3_f16(uint32_t* c, const uint32_t* a, const uint32_t* b) {
    asm volatile(
        "mma.sync.aligned.m16n8k32.row.col.f16.e4m3.e4m3.f16 "
        "{%0,%1}, {%2,%3,%4,%5}, {%6,%7}, {%0,%1};"
        : "+r"(c[0]), "+r"(c[1])
        : "r"(a[0]), "r"(a[1]), "r"(a[2]), "r"(a[3]), "r"(b[0]), "r"(b[1]));
}
__device__ __forceinline__ void cp16(uint32_t dst, const void* src) {
    asm volatile("cp.async.cg.shared.global [%0], [%1], 16;" :: "r"(dst), "l"(src) : "memory");
}
__device__ __forceinline__ void cp_commit() { asm volatile("cp.async.commit_group;" ::: "memory"); }
__device__ __forceinline__ void cp_wait0()  { asm volatile("cp.async.wait_group 0;" ::: "memory"); }
__device__ __forceinline__ void cp_wait1()  { asm volatile("cp.async.wait_group 1;" ::: "memory"); }

#define SROW 272   // 128 f16 row + 16B pad
#define FROW 144   // 128 fp8 row + 16B pad

// ============================================================
// Kernel 0a: weight convert to f16
// ============================================================
__global__ void wconv_kernel(const float* __restrict__ w1, const float* __restrict__ w2,
                             const float* __restrict__ w3, const float* __restrict__ w4)
{
    int idx = blockIdx.x * 256 + threadIdx.x;   // 131072 total
    if (idx < 98304) {
        int sel = idx >> 15, r = idx & 32767;
        const float* W = (sel == 0) ? w1 : (sel == 1) ? w2 : w3;
        d_wb[idx] = __float2half(W[r]);
    } else {
        int r = idx - 98304;
        d_w4b[r] = __float2half(w4[r]);
    }
}

// ============================================================
// Kernel 0b: x transpose-convert: [b][c][n] fp32 -> [b][n][c] f16
// ============================================================
__global__ void xT_kernel(const float* __restrict__ x)
{
    __shared__ float t[32][33];
    const int n0 = blockIdx.x * 32, c0 = blockIdx.y * 32, b = blockIdx.z;
    const float* xb = x + ((size_t)b * CDIM + c0) * NPIX + n0;
    for (int r = threadIdx.y; r < 32; r += 8)
        t[r][threadIdx.x] = xb[(size_t)r * NPIX + threadIdx.x];
    __syncthreads();
    __half* o = d_xT + ((size_t)b * NPIX + n0) * CDIM + c0;
    for (int r = threadIdx.y; r < 32; r += 8)
        o[(size_t)r * CDIM + threadIdx.x] = __float2half(t[threadIdx.x][r]);
}

// ============================================================
// Kernel 1: proj via mma (f16 in, f16 acc, 3 CTAs/SM). M=128, N=128, K=256
// as two sequential K=128 chunks. sel 0/1 -> thT8/phT8 e4m3 [n][m];
// sel 2 -> gu f16 [m][n].
// ============================================================
__global__ __launch_bounds__(256, 3) void proj_mma_kernel(
    const float* __restrict__ b1, const float* __restrict__ b2, const float* __restrict__ b3)
{
    extern __shared__ __align__(16) char smem[];
    char* Asm = smem;               // 128*272 = 34816
    char* Bsm = smem + 34816;
    const uint32_t Asb = smem_u32(Asm), Bsb = smem_u32(Bsm);

    const int tid = threadIdx.x, wid = tid >> 5, lane = tid & 31;
    const int n0 = blockIdx.x * 128, sel = blockIdx.y, b = blockIdx.z;
    const float* Bv = (sel == 0) ? b1 : (sel == 1) ? b2 : b3;

    const __half* W = d_wb + (size_t)sel * CHALF * CDIM;
    const __half* X = d_xT + ((size_t)b * NPIX + n0) * CDIM;

    const int wm = (wid & 3) * 32, wn = (wid >> 2) * 64;
    const int id = lane >> 3, l7 = lane & 7;

    uint32_t acc[2][8][2];   // f16x2 accumulators
#pragma unroll
    for (int am = 0; am < 2; ++am)
#pragma unroll
        for (int an = 0; an < 8; ++an) { acc[am][an][0] = 0u; acc[am][an][1] = 0u; }

#pragma unroll
    for (int kc = 0; kc < 2; ++kc) {
        if (kc) __syncthreads();
#pragma unroll
        for (int e = 0; e < 8; ++e) {
            int idx = e * 256 + tid;
            int row = idx >> 4, kb = idx & 15;
            cp16(Asb + row * SROW + kb * 16, W + (size_t)row * CDIM + kc * 128 + kb * 8);
            cp16(Bsb + row * SROW + kb * 16, X + (size_t)row * CDIM + kc * 128 + kb * 8);
        }
        cp_commit(); cp_wait0();
        __syncthreads();

#pragma unroll
        for (int ks = 0; ks < 8; ++ks) {
            uint32_t a[2][4];
#pragma unroll
            for (int am = 0; am < 2; ++am) {
                uint32_t addr = Asb + (uint32_t)(wm + am * 16 + (id & 1) * 8 + l7) * SROW
                              + (uint32_t)(ks * 16 + (id >> 1) * 8) * 2;
                ldm_x4(a[am][0], a[am][1], a[am][2], a[am][3], addr);
            }
            uint32_t bf[8][2];
#pragma unroll
            for (int p = 0; p < 4; ++p) {
                uint32_t r0, r1, r2, r3;
                uint32_t addr = Bsb + (uint32_t)(wn + p * 16 + (id >> 1) * 8 + l7) * SROW
                              + (uint32_t)(ks * 16 + (id & 1) * 8) * 2;
                ldm_x4(r0, r1, r2, r3, addr);
                bf[p * 2][0] = r0; bf[p * 2][1] = r1;
                bf[p * 2 + 1][0] = r2; bf[p * 2 + 1][1] = r3;
            }
#pragma unroll
            for (int am = 0; am < 2; ++am)
#pragma unroll
                for (int an = 0; an < 8; ++an)
                    mma_f16acc(acc[am][an], a[am], bf[an]);
        }
    }
    __syncthreads();

    char* Es = smem;
    const int gID = lane >> 2, tig = lane & 3;

    if (sel < 2) {
        // stage transposed [n][m] e4m3 (stride FROW), bias per m
#pragma unroll
        for (int am = 0; am < 2; ++am) {
            float bias0 = Bv[wm + am * 16 + gID];
            float bias1 = Bv[wm + am * 16 + gID + 8];
            int mm = wm + am * 16 + gID;
#pragma unroll
            for (int an = 0; an < 8; ++an) {
                int nn = wn + an * 8 + 2 * tig;
                float2 f0 = __half22float2(*(__half2*)&acc[am][an][0]);
                float2 f1 = __half22float2(*(__half2*)&acc[am][an][1]);
                *(uint8_t*)(Es + nn * FROW + mm)           = (uint8_t)(pack_e4m3x2(f0.x + bias0, 0.f) & 0xff);
                *(uint8_t*)(Es + (nn + 1) * FROW + mm)     = (uint8_t)(pack_e4m3x2(f0.y + bias0, 0.f) & 0xff);
                *(uint8_t*)(Es + nn * FROW + mm + 8)       = (uint8_t)(pack_e4m3x2(f1.x + bias1, 0.f) & 0xff);
                *(uint8_t*)(Es + (nn + 1) * FROW + mm + 8) = (uint8_t)(pack_e4m3x2(f1.y + bias1, 0.f) & 0xff);
            }
        }
        __syncthreads();
        uint8_t* O = ((sel == 0) ? d_thT8 : d_phT8) + (size_t)b * NPIX * CHALF;
#pragma unroll
        for (int e = 0; e < 4; ++e) {
            int idx = e * 256 + tid;
            int row = idx >> 3, kb = idx & 7;
            *(uint4*)(O + (size_t)(n0 + row) * CHALF + kb * 16) = *(const uint4*)(Es + row * FROW + kb * 16);
        }
    } else {
        // stage [m][n] f16 (stride 272), bias per m
#pragma unroll
        for (int am = 0; am < 2; ++am) {
            float bias0 = Bv[wm + am * 16 + gID];
            float bias1 = Bv[wm + am * 16 + gID + 8];
            int mm = wm + am * 16 + gID;
#pragma unroll
            for (int an = 0; an < 8; ++an) {
                int nn = wn + an * 8 + 2 * tig;
                float2 f0 = __half22float2(*(__half2*)&acc[am][an][0]);
                float2 f1 = __half22float2(*(__half2*)&acc[am][an][1]);
                *(uint32_t*)(Es + mm * SROW + nn * 2)       = pack_f16x2(f0.x + bias0, f0.y + bias0);
                *(uint32_t*)(Es + (mm + 8) * SROW + nn * 2) = pack_f16x2(f1.x + bias1, f1.y + bias1);
            }
        }
        __syncthreads();
        __half* O = d_gu + (size_t)b * CHALF * NPIX;
#pragma unroll
        for (int e = 0; e < 8; ++e) {
            int idx = e * 256 + tid;
            int row = idx >> 4, kb = idx & 15;
            *(uint4*)(O + (size_t)row * NPIX + n0 + kb * 8) = *(const uint4*)(Es + row * SROW + kb * 16);
        }
    }
}

// ============================================================
// Kernel 2: scores via fp8 mma (e4m3 in, f16 acc, 3 CTAs/SM).
// CTA tile 128(i) x 128(j), K=128 in 4 k32 steps.
// E -> e4m3 gmem; col sums (fp32) via shfl.
// smem: A 18432 | B 18432 | sums 2048 = 38912
// ============================================================
__global__ __launch_bounds__(256, 3) void scores_mma_kernel()
{
    extern __shared__ __align__(16) char smem[];
    char* Asm = smem;
    char* Bsm = smem + 18432;
    float* sums = (float*)(smem + 36864);
    const uint32_t Asb = smem_u32(Asm), Bsb = smem_u32(Bsm);

    const int tid = threadIdx.x, wid = tid >> 5, lane = tid & 31;
    const int j0 = blockIdx.x * 128, i0 = blockIdx.y * 128, b = blockIdx.z;

    const uint8_t* Ath = d_thT8 + ((size_t)b * NPIX + i0) * CHALF;
    const uint8_t* Bph = d_phT8 + ((size_t)b * NPIX + j0) * CHALF;

#pragma unroll
    for (int e = 0; e < 4; ++e) {
        int idx = e * 256 + tid;
        int row = idx >> 3, kb = idx & 7;
        cp16(Asb + row * FROW + kb * 16, Ath + (size_t)row * CHALF + kb * 16);
        cp16(Bsb + row * FROW + kb * 16, Bph + (size_t)row * CHALF + kb * 16);
    }
    cp_commit(); cp_wait0();
    __syncthreads();

    const int wm = (wid & 3) * 32, wn = (wid >> 2) * 64;
    const int id = lane >> 3, l7 = lane & 7;

    uint32_t acc[2][8][2];   // f16x2 accumulators
#pragma unroll
    for (int am = 0; am < 2; ++am)
#pragma unroll
        for (int an = 0; an < 8; ++an) { acc[am][an][0] = 0u; acc[am][an][1] = 0u; }

#pragma unroll
    for (int ks = 0; ks < 4; ++ks) {
        uint32_t a[2][4];
#pragma unroll
        for (int am = 0; am < 2; ++am) {
            uint32_t addr = Asb + (uint32_t)(wm + am * 16 + (id & 1) * 8 + l7) * FROW
                          + (uint32_t)(ks * 32 + (id >> 1) * 16);
            ldm_x4(a[am][0], a[am][1], a[am][2], a[am][3], addr);
        }
        uint32_t bf[8][2];
#pragma unroll
        for (int p = 0; p < 4; ++p) {
            uint32_t r0, r1, r2, r3;
            uint32_t addr = Bsb + (uint32_t)(wn + p * 16 + (id >> 1) * 8 + l7) * FROW
                          + (uint32_t)(ks * 32 + (id & 1) * 16);
            ldm_x4(r0, r1, r2, r3, addr);
            bf[p * 2][0] = r0; bf[p * 2][1] = r1;
            bf[p * 2 + 1][0] = r2; bf[p * 2 + 1][1] = r3;
        }
#pragma unroll
        for (int am = 0; am < 2; ++am)
#pragma unroll
            for (int an = 0; an < 8; ++an)
                mma_e4m3_f16(acc[am][an], a[am], bf[an]);
    }
    __syncthreads();   // tile reads done; reuse smem as staging

    // epilogue: per-fragment exp -> stage e4m3 E (stride FROW) + running col sums
    char* Es = smem;
    const int gID = lane >> 2, tig = lane & 3;
    float s[8][2];
#pragma unroll
    for (int an = 0; an < 8; ++an) { s[an][0] = 0.f; s[an][1] = 0.f; }

#pragma unroll
    for (int am = 0; am < 2; ++am)
#pragma unroll
        for (int an = 0; an < 8; ++an) {
            float2 f0 = __half22float2(*(__half2*)&acc[am][an][0]);
            float2 f1 = __half22float2(*(__half2*)&acc[am][an][1]);
            float e0 = __expf(f0.x), e1 = __expf(f0.y);
            float e2 = __expf(f1.x), e3 = __expf(f1.y);
            int m0 = wm + am * 16, n0 = wn + an * 8 + 2 * tig;
            *(uint16_t*)(Es + (m0 + gID) * FROW + n0)     = pack_e4m3x2(e0, e1);
            *(uint16_t*)(Es + (m0 + gID + 8) * FROW + n0) = pack_e4m3x2(e2, e3);
            s[an][0] += e0 + e2;
            s[an][1] += e1 + e3;
        }

#pragma unroll
    for (int an = 0; an < 8; ++an) {
        float s0 = s[an][0], s1 = s[an][1];
        s0 += __shfl_xor_sync(0xffffffffu, s0, 4);
        s0 += __shfl_xor_sync(0xffffffffu, s0, 8);
        s0 += __shfl_xor_sync(0xffffffffu, s0, 16);
        s1 += __shfl_xor_sync(0xffffffffu, s1, 4);
        s1 += __shfl_xor_sync(0xffffffffu, s1, 8);
        s1 += __shfl_xor_sync(0xffffffffu, s1, 16);
        if (lane < 4) {
            int col = wn + an * 8 + 2 * lane;
            sums[(wid & 3) * 128 + col]     = s0;
            sums[(wid & 3) * 128 + col + 1] = s1;
        }
    }
    __syncthreads();

    // write E tile (coalesced) + den partials
    uint8_t* Eb = d_E + ((size_t)b * NPIX + i0) * NPIX + j0;
#pragma unroll
    for (int e = 0; e < 4; ++e) {
        int idx = e * 256 + tid;
        int row = idx >> 3, kb = idx & 7;
        *(uint4*)(Eb + (size_t)row * NPIX + kb * 16) = *(const uint4*)(Es + row * FROW + kb * 16);
    }
    if (tid < 128)
        d_denp[((size_t)b * 32 + blockIdx.y) * NPIX + j0 + tid]
            = sums[tid] + sums[128 + tid] + sums[256 + tid] + sums[384 + tid];
}

// ============================================================
// Kernel 3: den reduce over 32 i-tile partials (deterministic, float4)
// ============================================================
__global__ void den_reduce_kernel()
{
    int j = blockIdx.x * 1024 + threadIdx.x * 4;
    int b = blockIdx.y;
    float4 s = make_float4(0.f, 0.f, 0.f, 0.f);
#pragma unroll
    for (int t = 0; t < 32; ++t) {
        float4 v = *(const float4*)&d_denp[((size_t)b * 32 + t) * NPIX + j];
        s.x += v.x; s.y += v.y; s.z += v.z; s.w += v.w;
    }
    *(float4*)&d_den[b * NPIX + j] = s;
}

// ============================================================
// Kernel 4: gs8[b][c][j] = e4m3(gu[b][c][j] * 4096 / den[j])
// ============================================================
__global__ void gscale_kernel()
{
    int idx = blockIdx.x * 256 + threadIdx.x;
    int j  = (idx & (NPIX / 8 - 1)) * 8;
    int c  = (idx >> 9) & (CHALF - 1);
    int b  = idx >> 16;
    size_t off = ((size_t)b * CHALF + c) * NPIX + j;
    uint4 gv = *(const uint4*)(d_gu + off);
    const float* dp = d_den + b * NPIX + j;
    float4 e0 = *(const float4*)&dp[0], e1 = *(const float4*)&dp[4];
    const uint32_t* h = (const uint32_t*)&gv;
    float gf[8];
#pragma unroll
    for (int q = 0; q < 4; ++q) {
        float2 f = __half22float2(*(__half2*)&h[q]);
        gf[2 * q] = f.x; gf[2 * q + 1] = f.y;
    }
    uint32_t w0 = (uint32_t)pack_e4m3x2(gf[0] * 4096.f / e0.x, gf[1] * 4096.f / e0.y)
                | ((uint32_t)pack_e4m3x2(gf[2] * 4096.f / e0.z, gf[3] * 4096.f / e0.w) << 16);
    uint32_t w1 = (uint32_t)pack_e4m3x2(gf[4] * 4096.f / e1.x, gf[5] * 4096.f / e1.y)
                | ((uint32_t)pack_e4m3x2(gf[6] * 4096.f / e1.z, gf[7] * 4096.f / e1.w) << 16);
    *(uint2*)(d_gs8 + off) = make_uint2(w0, w1);
}

// ============================================================
// Kernel 5 (FUSED y + out): y via fp8 mma (3-stage pipeline), then
// out = w4*y + b4 + x in-CTA.
// smem: 3 stages x 36864 = 110592. Post-loop: y @0 (34816), w4 @36864 (+69632).
// ============================================================
__global__ __launch_bounds__(256) void y_out_kernel(
    const float* __restrict__ x, const float* __restrict__ b4, float* __restrict__ out)
{
    extern __shared__ __align__(16) char smem[];
    const uint32_t sb = smem_u32(smem);

    const int tid = threadIdx.x, wid = tid >> 5, lane = tid & 31;
    const int i0 = blockIdx.x * 128, b = blockIdx.y;

    const uint8_t* Ebase = d_E   + ((size_t)b * NPIX + i0) * NPIX;
    const uint8_t* Gbase = d_gs8 + (size_t)b * CHALF * NPIX;

    const int wm = (wid & 3) * 32, wn = (wid >> 2) * 64;
    const int id = lane >> 3, l7 = lane & 7;

    float accf[2][8][4];
#pragma unroll
    for (int am = 0; am < 2; ++am)
#pragma unroll
        for (int an = 0; an < 8; ++an)
#pragma unroll
            for (int q = 0; q < 4; ++q) accf[am][an][q] = 0.f;

    auto issue_chunk = [&](int c) {
        uint32_t st = sb + (uint32_t)(c % 3) * 36864;
        size_t k0 = (size_t)c * 128;
#pragma unroll
        for (int e = 0; e < 4; ++e) {
            int idx = e * 256 + tid;
            int row = idx >> 3, kb = idx & 7;
            cp16(st + row * FROW + kb * 16,         Ebase + (size_t)row * NPIX + k0 + kb * 16);
            cp16(st + 18432 + row * FROW + kb * 16, Gbase + (size_t)row * NPIX + k0 + kb * 16);
        }
    };

    issue_chunk(0); cp_commit();
    issue_chunk(1); cp_commit();

    for (int c = 0; c < 32; ++c) {
        if (c < 31) cp_wait1(); else cp_wait0();
        __syncthreads();
        if (c + 2 < 32) { issue_chunk(c + 2); cp_commit(); }

        uint32_t Ab = sb + (uint32_t)(c % 3) * 36864;
        uint32_t Bb = Ab + 18432;
#pragma unroll
        for (int ks = 0; ks < 4; ++ks) {            // k32 steps over 128
            uint32_t a[2][4];
#pragma unroll
            for (int am = 0; am < 2; ++am) {
                uint32_t addr = Ab + (uint32_t)(wm + am * 16 + (id & 1) * 8 + l7) * FROW
                              + (uint32_t)(ks * 32 + (id >> 1) * 16);
                ldm_x4(a[am][0], a[am][1], a[am][2], a[am][3], addr);
            }
            uint32_t bf[8][2];
#pragma unroll
            for (int p = 0; p < 4; ++p) {
                uint32_t r0, r1, r2, r3;
                uint32_t addr = Bb + (uint32_t)(wn + p * 16 + (id >> 1) * 8 + l7) * FROW
                              + (uint32_t)(ks * 32 + (id & 1) * 16);
                ldm_x4(r0, r1, r2, r3, addr);
                bf[p * 2][0] = r0; bf[p * 2][1] = r1;
                bf[p * 2 + 1][0] = r2; bf[p * 2 + 1][1] = r3;
            }
#pragma unroll
            for (int am = 0; am < 2; ++am)
#pragma unroll
                for (int an = 0; an < 8; ++an)
                    mma_e4m3(accf[am][an], a[am], bf[an]);
        }
    }
    __syncthreads();   // mainloop smem free

    // stage y = accf * (1/4096) as f16 [m=i][n=c] at smem+0;
    // concurrently cp.async w4 [256][128] f16 into smem+36864
    const float S = 1.f / 4096.f;
    char* Ys = smem;
    const uint32_t Wb = sb + 36864;
    const int gID = lane >> 2, tig = lane & 3;
#pragma unroll
    for (int e = 0; e < 16; ++e) {
        int idx = e * 256 + tid;
        int row = idx >> 4, kb = idx & 15;
        cp16(Wb + row * SROW + kb * 16, d_w4b + (size_t)row * CHALF + kb * 8);
    }
    cp_commit();
#pragma unroll
    for (int am = 0; am < 2; ++am)
#pragma unroll
        for (int an = 0; an < 8; ++an) {
            int mm = wm + am * 16 + gID, nn = wn + an * 8 + 2 * tig;
            *(uint32_t*)(Ys + mm * SROW + nn * 2)       = pack_f16x2(accf[am][an][0] * S, accf[am][an][1] * S);
            *(uint32_t*)(Ys + (mm + 8) * SROW + nn * 2) = pack_f16x2(accf[am][an][2] * S, accf[am][an][3] * S);
        }
    cp_wait0();
    __syncthreads();

    // out GEMM: two o-halves of 128. A = w4 rows (o), B = y rows (i), K = c.
    const uint32_t Yb = sb;
    for (int h = 0; h < 2; ++h) {
        int o0 = h * 128;
        float acc2[2][8][4];
#pragma unroll
        for (int am = 0; am < 2; ++am)
#pragma unroll
            for (int an = 0; an < 8; ++an)
#pragma unroll
                for (int q = 0; q < 4; ++q) acc2[am][an][q] = 0.f;

#pragma unroll
        for (int ks = 0; ks < 8; ++ks) {
            uint32_t a[2][4];
#pragma unroll
            for (int am = 0; am < 2; ++am) {
                uint32_t addr = Wb + (uint32_t)(o0 + wm + am * 16 + (id & 1) * 8 + l7) * SROW
                              + (uint32_t)(ks * 16 + (id >> 1) * 8) * 2;
                ldm_x4(a[am][0], a[am][1], a[am][2], a[am][3], addr);
            }
            uint32_t bf[8][2];
#pragma unroll
            for (int p = 0; p < 4; ++p) {
                uint32_t r0, r1, r2, r3;
                uint32_t addr = Yb + (uint32_t)(wn + p * 16 + (id >> 1) * 8 + l7) * SROW
                              + (uint32_t)(ks * 16 + (id & 1) * 8) * 2;
                ldm_x4(r0, r1, r2, r3, addr);
                bf[p * 2][0] = r0; bf[p * 2][1] = r1;
                bf[p * 2 + 1][0] = r2; bf[p * 2 + 1][1] = r3;
            }
#pragma unroll
            for (int am = 0; am < 2; ++am)
#pragma unroll
                for (int an = 0; an < 8; ++an)
                    mma_f16(acc2[am][an], a[am], bf[an]);
        }

#pragma unroll
        for (int am = 0; am < 2; ++am) {
            int mo0 = o0 + wm + am * 16 + gID;
            int mo1 = mo0 + 8;
            float bias0 = b4[mo0], bias1 = b4[mo1];
#pragma unroll
            for (int an = 0; an < 8; ++an) {
                int nn = i0 + wn + an * 8 + 2 * tig;
                size_t off0 = ((size_t)b * CDIM + mo0) * NPIX + nn;
                size_t off1 = ((size_t)b * CDIM + mo1) * NPIX + nn;
                float2 x0 = *(const float2*)&x[off0];
                float2 x1 = *(const float2*)&x[off1];
                *(float2*)&out[off0] = make_float2(acc2[am][an][0] + bias0 + x0.x,
                                                   acc2[am][an][1] + bias0 + x0.y);
                *(float2*)&out[off1] = make_float2(acc2[am][an][2] + bias1 + x1.x,
                                                   acc2[am][an][3] + bias1 + x1.y);
            }
        }
    }
}

// ============================================================
extern "C" void kernel_launch(void* const* d_in, const int* in_sizes, int n_in,
                              void* d_out, int out_size)
{
    const float* x  = (const float*)d_in[0];
    const float* w1 = (const float*)d_in[1];
    const float* b1 = (const float*)d_in[2];
    const float* w2 = (const float*)d_in[3];
    const float* b2 = (const float*)d_in[4];
    const float* w3 = (const float*)d_in[5];
    const float* b3 = (const float*)d_in[6];
    const float* w4 = (const float*)d_in[7];
    const float* b4 = (const float*)d_in[8];
    float* out = (float*)d_out;

    const int P_SMEM  = 2 * 128 * SROW;            // 69632 (3 CTAs/SM)
    const int SC_SMEM = 2 * 128 * FROW + 2048;     // 38912 (3 CTAs/SM, reg-capped)
    const int Y_SMEM  = 3 * 2 * 128 * FROW;        // 110592
    cudaFuncSetAttribute(proj_mma_kernel,   cudaFuncAttributeMaxDynamicSharedMemorySize, P_SMEM);
    cudaFuncSetAttribute(scores_mma_kernel, cudaFuncAttributeMaxDynamicSharedMemorySize, SC_SMEM);
    cudaFuncSetAttribute(y_out_kernel,      cudaFuncAttributeMaxDynamicSharedMemorySize, Y_SMEM);

    wconv_kernel     <<<512, 256>>>(w1, w2, w3, w4);
    xT_kernel        <<<dim3(NPIX / 32, CDIM / 32, BATCH), dim3(32, 8)>>>(x);
    proj_mma_kernel  <<<dim3(NPIX / 128, 3, BATCH), 256, P_SMEM>>>(b1, b2, b3);
    scores_mma_kernel<<<dim3(NPIX / 128, NPIX / 128, BATCH), 256, SC_SMEM>>>();
    den_reduce_kernel<<<dim3(NPIX / 1024, BATCH), 256>>>();
    gscale_kernel    <<<dim3(1024), 256>>>();
    y_out_kernel     <<<dim3(NPIX / 128, BATCH), 256, Y_SMEM>>>(x, b4, out);
}